// round 5
// baseline (speedup 1.0000x reference)
#include <cuda_runtime.h>
#include <math.h>
#include <stdint.h>

// Problem constants
#define HEI   256
#define WID   256
#define HW    65536
#define CIN   192
#define C3    576
#define NB    4
#define NHEADS 8
#define HDIM  24

// ---------------- device scratch ----------------
__device__ __align__(256) float g_qkv [(size_t)NB * C3 * HW];
__device__ __align__(256) float g_qkvd[(size_t)NB * C3 * HW];   // only v region used now
__device__ __align__(256) float g_gram[NB * NHEADS * HDIM * HDIM];
__device__ __align__(256) float g_sums[NB * 2 * CIN];
__device__ __align__(256) float g_M   [NB * CIN * CIN];

__device__ __forceinline__ uint32_t to_tf32_bits(float x) {
    uint32_t y; asm("cvt.rna.tf32.f32 %0, %1;" : "=r"(y) : "f"(x)); return y;
}

__device__ __forceinline__ void mma_tf32_16x8x8(
    float& c0, float& c1, float& c2, float& c3,
    uint32_t a0, uint32_t a1, uint32_t a2, uint32_t a3,
    uint32_t b0, uint32_t b1)
{
    asm volatile(
        "mma.sync.aligned.m16n8k8.row.col.f32.tf32.tf32.f32 "
        "{%0,%1,%2,%3}, {%4,%5,%6,%7}, {%8,%9}, {%0,%1,%2,%3};"
        : "+f"(c0), "+f"(c1), "+f"(c2), "+f"(c3)
        : "r"(a0), "r"(a1), "r"(a2), "r"(a3), "r"(b0), "r"(b1));
}

// ---------------- zero small accumulators ----------------
__global__ void zero_small_kernel() {
    int i = blockIdx.x * 256 + threadIdx.x;
    if (i < NB * NHEADS * HDIM * HDIM) g_gram[i] = 0.0f;
    if (i < NB * 2 * CIN)              g_sums[i] = 0.0f;
}

// ---------------- tf32 mma.sync GEMM ----------------
// C[M=channels, N=pixels] = A[M,K] @ B[K,N], K=192.
// Block: BM=192, BN=128, BK=32, 256 thr = 8 warps (4M x 2N), warp tile 48x64.
#define BM 192
#define BN 128
#define BK 32
#define AS_STRIDE 36
#define BS_STRIDE 136
#define AS_FLOATS (BM * AS_STRIDE)
#define BS_FLOATS (BK * BS_STRIDE)
#define STAGE_FLOATS (AS_FLOATS + BS_FLOATS)
#define GEMM_SMEM_BYTES (2 * STAGE_FLOATS * 4)   // 90112

template <int MODE>
__global__ void __launch_bounds__(256) gemm_mma_kernel(
    const float* __restrict__ xin, const float* __restrict__ win, float* __restrict__ outp)
{
    extern __shared__ float smem[];
    const int tid  = threadIdx.x;
    const int b    = blockIdx.z;
    const int pix0 = blockIdx.x * BN;

    const float* Ag; const float* Bg; float* Cg;
    if (MODE == 0) {
        const int m0 = blockIdx.y * BM;
        Ag = win + (size_t)m0 * CIN;
        Bg = xin + (size_t)b * CIN * HW;
        Cg = g_qkv + ((size_t)b * C3 + m0) * HW;
    } else {
        Ag = g_M + (size_t)b * CIN * CIN;
        Bg = g_qkvd + ((size_t)b * C3 + 2 * CIN) * HW;
        Cg = outp + (size_t)b * CIN * HW;
    }

    const int warp  = tid >> 5;
    const int lane  = tid & 31;
    const int warpM = warp >> 1;
    const int warpN = warp & 1;
    const int m0w   = warpM * 48;
    const int n0w   = warpN * 64;
    const int g     = lane >> 2;
    const int cq    = lane & 3;

    const int a_row = tid >> 3;
    const int a_kq  = (tid & 7) * 4;
    const int b_kr  = tid >> 5;
    const int b_n4  = lane * 4;

    float4 areg[6], breg[4];

    auto loadA = [&](int t) {
#pragma unroll
        for (int i = 0; i < 6; i++)
            areg[i] = *(const float4*)&Ag[(size_t)(a_row + i * 32) * CIN + t * BK + a_kq];
    };
    auto loadB = [&](int t) {
#pragma unroll
        for (int i = 0; i < 4; i++)
            breg[i] = *(const float4*)&Bg[(size_t)(t * BK + b_kr + i * 8) * HW + pix0 + b_n4];
    };
    auto storeA = [&](int s) {
        float* As = smem + s * STAGE_FLOATS;
#pragma unroll
        for (int i = 0; i < 6; i++) {
            uint32_t* p = (uint32_t*)&As[(a_row + i * 32) * AS_STRIDE + a_kq];
            p[0] = to_tf32_bits(areg[i].x); p[1] = to_tf32_bits(areg[i].y);
            p[2] = to_tf32_bits(areg[i].z); p[3] = to_tf32_bits(areg[i].w);
        }
    };
    auto storeB = [&](int s) {
        float* Bs = smem + s * STAGE_FLOATS + AS_FLOATS;
#pragma unroll
        for (int i = 0; i < 4; i++) {
            uint32_t* p = (uint32_t*)&Bs[(b_kr + i * 8) * BS_STRIDE + b_n4];
            p[0] = to_tf32_bits(breg[i].x); p[1] = to_tf32_bits(breg[i].y);
            p[2] = to_tf32_bits(breg[i].z); p[3] = to_tf32_bits(breg[i].w);
        }
    };

    float c[3][8][4];
#pragma unroll
    for (int i = 0; i < 3; i++)
#pragma unroll
        for (int j = 0; j < 8; j++)
#pragma unroll
            for (int q = 0; q < 4; q++) c[i][j][q] = 0.0f;

    loadA(0); loadB(0);
    storeA(0); storeB(0);
    __syncthreads();

#pragma unroll 1
    for (int t = 0; t < 6; t++) {
        if (t < 5) { loadA(t + 1); loadB(t + 1); }
        const int s = t & 1;
        const uint32_t* As = (const uint32_t*)(smem + s * STAGE_FLOATS);
        const uint32_t* Bs = (const uint32_t*)(smem + s * STAGE_FLOATS + AS_FLOATS);
#pragma unroll
        for (int kk = 0; kk < 4; kk++) {
            const int kb = kk * 8;
            uint32_t af[3][4], bf[8][2];
#pragma unroll
            for (int ms = 0; ms < 3; ms++) {
                const int mrow = m0w + ms * 16 + g;
                af[ms][0] = As[(mrow)     * AS_STRIDE + kb + cq];
                af[ms][1] = As[(mrow + 8) * AS_STRIDE + kb + cq];
                af[ms][2] = As[(mrow)     * AS_STRIDE + kb + cq + 4];
                af[ms][3] = As[(mrow + 8) * AS_STRIDE + kb + cq + 4];
            }
#pragma unroll
            for (int ns = 0; ns < 8; ns++) {
                const int ncol = n0w + ns * 8 + g;
                bf[ns][0] = Bs[(kb + cq)     * BS_STRIDE + ncol];
                bf[ns][1] = Bs[(kb + cq + 4) * BS_STRIDE + ncol];
            }
#pragma unroll
            for (int ms = 0; ms < 3; ms++)
#pragma unroll
                for (int ns = 0; ns < 8; ns++)
                    mma_tf32_16x8x8(c[ms][ns][0], c[ms][ns][1], c[ms][ns][2], c[ms][ns][3],
                                    af[ms][0], af[ms][1], af[ms][2], af[ms][3],
                                    bf[ns][0], bf[ns][1]);
        }
        if (t < 5) {
            storeA((t + 1) & 1); storeB((t + 1) & 1);
            __syncthreads();
        }
    }

#pragma unroll
    for (int ms = 0; ms < 3; ms++) {
        const int m = m0w + ms * 16 + g;
#pragma unroll
        for (int ns = 0; ns < 8; ns++) {
            const int n = pix0 + n0w + ns * 8 + cq * 2;
            *(float2*)&Cg[(size_t)m * HW + n]       = make_float2(c[ms][ns][0], c[ms][ns][1]);
            *(float2*)&Cg[(size_t)(m + 8) * HW + n] = make_float2(c[ms][ns][2], c[ms][ns][3]);
        }
    }
}

// ---------------- depthwise 3x3, v channels only ----------------
__global__ void __launch_bounds__(256) dwconv_v_kernel(const float* __restrict__ w)
{
    const int bc = blockIdx.x;               // b*CIN + c
    const int b  = bc / CIN;
    const int ch = 2 * CIN + (bc % CIN);
    const float* ip = g_qkv  + ((size_t)b * C3 + ch) * HW;
    float*       op = g_qkvd + ((size_t)b * C3 + ch) * HW;

    __shared__ float s[34][258];
    const int tid = threadIdx.x;
    const int y0  = blockIdx.y * 32;

    for (int i = tid; i < 34 * 256; i += 256) {
        const int r = i >> 8, xc = i & 255;
        const int y = y0 + r - 1;
        s[r][xc + 1] = (y >= 0 && y < HEI) ? ip[y * WID + xc] : 0.0f;
    }
    if (tid < 34) { s[tid][0] = 0.0f; s[tid][257] = 0.0f; }

    float wr[9];
#pragma unroll
    for (int i = 0; i < 9; i++) wr[i] = w[ch * 9 + i];
    __syncthreads();

#pragma unroll 4
    for (int r = 0; r < 32; r++) {
        float acc = 0.0f;
#pragma unroll
        for (int dy = 0; dy < 3; dy++)
#pragma unroll
            for (int dx = 0; dx < 3; dx++)
                acc = fmaf(s[r + dy][tid + dx], wr[dy * 3 + dx], acc);
        op[(y0 + r) * WID + tid] = acc;
    }
}

// ---------------- fused q/k dwconv + sumsq + gram (3xTF32) ----------------
// One block per (b, head, 32x8 pixel tile). q,k conv results never touch DRAM.
#define QKS 260                     // smem pixel stride (260 % 32 == 4 -> conflict-free)
#define SM_KBUF  (32 * QKS)         // qbuf rows 0..31 (24..31 zero pad)
#define SM_HALO  (SM_KBUF + 24 * QKS)
#define SM_WSM   (SM_HALO + 720)
#define SM_PART  (SM_WSM + 432)
#define SM_RED   (SM_PART + 384)
#define QK_SMEM_BYTES ((SM_RED + 8 * HDIM * HDIM) * 4)

__global__ void __launch_bounds__(256) qk_fused_kernel(const float* __restrict__ dw)
{
    extern __shared__ float sm[];
    float* qbuf = sm;                 // [32][260]
    float* kbuf = sm + SM_KBUF;       // [24][260]
    float* halo = sm + SM_HALO;       // [2][10][36]
    float* wsm  = sm + SM_WSM;        // 48*9 weights
    float* part = sm + SM_PART;       // [48][8] sumsq partials
    float* red  = sm + SM_RED;        // [8][576] gram partials

    const int bh = blockIdx.y;
    const int b = bh >> 3, h = bh & 7;
    const int tile = blockIdx.x;
    const int y0 = (tile >> 3) * 8;
    const int x0 = (tile & 7) * 32;

    const int tid  = threadIdx.x;
    const int warp = tid >> 5;
    const int lane = tid & 31;
    const int g    = lane >> 2;
    const int cq   = lane & 3;
    const int px   = lane;            // x in tile (0..31)
    const int py   = warp;            // y in tile (0..7)

    // zero qbuf pad rows 24..31; preload the 48 channels' weights
    for (int i = tid; i < 8 * QKS; i += 256) qbuf[24 * QKS + i] = 0.0f;
    for (int i = tid; i < 432; i += 256) {
        wsm[i] = (i < 216) ? dw[(h * HDIM) * 9 + i]
                           : dw[(CIN + h * HDIM) * 9 + (i - 216)];
    }

#pragma unroll 1
    for (int d = 0; d < HDIM; d++) {
        const int chq = h * HDIM + d;
        const int chk = CIN + chq;
        const float* ipq = g_qkv + ((size_t)b * C3 + chq) * HW;
        const float* ipk = g_qkv + ((size_t)b * C3 + chk) * HW;
        __syncthreads();
        for (int i = tid; i < 720; i += 256) {
            const int which = i / 360, rem = i % 360;
            const int r = rem / 36, cc = rem % 36;
            float v = 0.0f;
            if (cc < 34) {
                const int gy = y0 + r - 1, gx = x0 + cc - 1;
                if (gy >= 0 && gy < HEI && gx >= 0 && gx < WID)
                    v = (which ? ipk : ipq)[gy * WID + gx];
            }
            halo[i] = v;
        }
        __syncthreads();
        float aq = 0.0f, ak = 0.0f;
#pragma unroll
        for (int dy = 0; dy < 3; dy++)
#pragma unroll
            for (int dx = 0; dx < 3; dx++) {
                const int hoff = (py + dy) * 36 + px + dx;
                const int widx = d * 9 + dy * 3 + dx;
                aq = fmaf(halo[hoff],       wsm[widx],       aq);
                ak = fmaf(halo[360 + hoff], wsm[216 + widx], ak);
            }
        qbuf[d * QKS + tid] = aq;
        kbuf[d * QKS + tid] = ak;
        float sq = aq * aq, sk = ak * ak;
#pragma unroll
        for (int o = 16; o; o >>= 1) {
            sq += __shfl_down_sync(0xffffffffu, sq, o);
            sk += __shfl_down_sync(0xffffffffu, sk, o);
        }
        if (lane == 0) { part[d * 8 + warp] = sq; part[(HDIM + d) * 8 + warp] = sk; }
    }
    __syncthreads();

    if (tid < 48) {
        float s = 0.0f;
#pragma unroll
        for (int w2 = 0; w2 < 8; w2++) s += part[tid * 8 + w2];
        const int d = (tid >= HDIM) ? tid - HDIM : tid;
        atomicAdd(&g_sums[b * 2 * CIN + (tid >= HDIM ? CIN : 0) + h * HDIM + d], s);
    }

    // gram: G += q(24x256) @ k(24x256)^T, warp w covers pixels [w*32, w*32+32)
    float c[2][3][4];
#pragma unroll
    for (int mt = 0; mt < 2; mt++)
#pragma unroll
        for (int nt = 0; nt < 3; nt++)
#pragma unroll
            for (int q = 0; q < 4; q++) c[mt][nt][q] = 0.0f;

#pragma unroll
    for (int k8 = 0; k8 < 4; k8++) {
        const int kb8 = warp * 32 + k8 * 8;
        uint32_t ah[2][4], al[2][4], bh2[3][2], bl[3][2];
#pragma unroll
        for (int mt = 0; mt < 2; mt++) {
            const int r0 = mt * 16 + g;
#pragma unroll
            for (int q = 0; q < 4; q++) {
                const int rr = r0 + (q & 1) * 8;
                const int cc = kb8 + cq + (q >> 1) * 4;
                const float v = qbuf[rr * QKS + cc];
                ah[mt][q] = to_tf32_bits(v);
                al[mt][q] = to_tf32_bits(v - __uint_as_float(ah[mt][q]));
            }
        }
#pragma unroll
        for (int nt = 0; nt < 3; nt++) {
            const int er = nt * 8 + g;
#pragma unroll
            for (int q = 0; q < 2; q++) {
                const float v = kbuf[er * QKS + kb8 + cq + q * 4];
                bh2[nt][q] = to_tf32_bits(v);
                bl[nt][q]  = to_tf32_bits(v - __uint_as_float(bh2[nt][q]));
            }
        }
#pragma unroll
        for (int mt = 0; mt < 2; mt++)
#pragma unroll
            for (int nt = 0; nt < 3; nt++) {
                mma_tf32_16x8x8(c[mt][nt][0], c[mt][nt][1], c[mt][nt][2], c[mt][nt][3],
                                ah[mt][0], ah[mt][1], ah[mt][2], ah[mt][3],
                                bh2[nt][0], bh2[nt][1]);
                mma_tf32_16x8x8(c[mt][nt][0], c[mt][nt][1], c[mt][nt][2], c[mt][nt][3],
                                ah[mt][0], ah[mt][1], ah[mt][2], ah[mt][3],
                                bl[nt][0], bl[nt][1]);
                mma_tf32_16x8x8(c[mt][nt][0], c[mt][nt][1], c[mt][nt][2], c[mt][nt][3],
                                al[mt][0], al[mt][1], al[mt][2], al[mt][3],
                                bh2[nt][0], bh2[nt][1]);
            }
    }

    float* rw = red + warp * (HDIM * HDIM);
#pragma unroll
    for (int mt = 0; mt < 2; mt++) {
        const int d = mt * 16 + g;
#pragma unroll
        for (int nt = 0; nt < 3; nt++) {
            const int e = nt * 8 + cq * 2;
            rw[d * HDIM + e]     = c[mt][nt][0];
            rw[d * HDIM + e + 1] = c[mt][nt][1];
            if (d + 8 < HDIM) {
                rw[(d + 8) * HDIM + e]     = c[mt][nt][2];
                rw[(d + 8) * HDIM + e + 1] = c[mt][nt][3];
            }
        }
    }
    __syncthreads();
    for (int i = tid; i < HDIM * HDIM; i += 256) {
        float s = 0.0f;
#pragma unroll
        for (int w2 = 0; w2 < 8; w2++) s += red[w2 * (HDIM * HDIM) + i];
        atomicAdd(&g_gram[bh * HDIM * HDIM + i], s);
    }
}

// ---------------- softmax + fold projection: M = proj * blockdiag(attn) ----------------
__global__ void __launch_bounds__(256) attn_proj_kernel(
    const float* __restrict__ temp, const float* __restrict__ projw)
{
    const int h = blockIdx.x, b = blockIdx.y;
    __shared__ float attn[HDIM][HDIM];
    __shared__ float nq[HDIM], nk[HDIM];
    const int tid = threadIdx.x;

    if (tid < HDIM) {
        nq[tid] = fmaxf(sqrtf(g_sums[b * 2 * CIN + h * HDIM + tid]), 1e-12f);
        nk[tid] = fmaxf(sqrtf(g_sums[b * 2 * CIN + CIN + h * HDIM + tid]), 1e-12f);
    }
    __syncthreads();

    if (tid < HDIM) {
        const float t = temp[h];
        const float* gg = g_gram + ((b * NHEADS + h) * HDIM + tid) * HDIM;
        float row[HDIM];
        float mx = -1e30f;
        const float inq = 1.0f / nq[tid];
#pragma unroll
        for (int e = 0; e < HDIM; e++) {
            row[e] = gg[e] * t * inq / nk[e];
            mx = fmaxf(mx, row[e]);
        }
        float ssum = 0.0f;
#pragma unroll
        for (int e = 0; e < HDIM; e++) { row[e] = expf(row[e] - mx); ssum += row[e]; }
        const float inv = 1.0f / ssum;
#pragma unroll
        for (int e = 0; e < HDIM; e++) attn[tid][e] = row[e] * inv;
    }
    __syncthreads();

    for (int idx = tid; idx < CIN * HDIM; idx += 256) {
        const int o = idx / HDIM, e = idx % HDIM;
        float ssum = 0.0f;
#pragma unroll
        for (int d = 0; d < HDIM; d++)
            ssum = fmaf(projw[o * CIN + h * HDIM + d], attn[d][e], ssum);
        g_M[(size_t)b * CIN * CIN + o * CIN + h * HDIM + e] = ssum;
    }
}

// ---------------- launch ----------------
extern "C" void kernel_launch(void* const* d_in, const int* in_sizes, int n_in,
                              void* d_out, int out_size)
{
    const float *x = nullptr, *qkvw = nullptr, *dww = nullptr, *projw = nullptr, *temp = nullptr;
    for (int i = 0; i < n_in; i++) {
        switch (in_sizes[i]) {
            case NB * CIN * HW:   x     = (const float*)d_in[i]; break;
            case C3 * CIN:        qkvw  = (const float*)d_in[i]; break;
            case C3 * 9:          dww   = (const float*)d_in[i]; break;
            case CIN * CIN:       projw = (const float*)d_in[i]; break;
            case NHEADS:          temp  = (const float*)d_in[i]; break;
        }
    }
    float* out = (float*)d_out;

    static int configured = 0;
    if (!configured) {
        cudaFuncSetAttribute(gemm_mma_kernel<0>, cudaFuncAttributeMaxDynamicSharedMemorySize, GEMM_SMEM_BYTES);
        cudaFuncSetAttribute(gemm_mma_kernel<1>, cudaFuncAttributeMaxDynamicSharedMemorySize, GEMM_SMEM_BYTES);
        cudaFuncSetAttribute(qk_fused_kernel, cudaFuncAttributeMaxDynamicSharedMemorySize, QK_SMEM_BYTES);
        configured = 1;
    }

    zero_small_kernel<<<72, 256>>>();

    // qkv 1x1 conv (pixel tiles fastest -- R3 order)
    gemm_mma_kernel<0><<<dim3(HW / BN, 3, NB), 256, GEMM_SMEM_BYTES>>>(x, qkvw, nullptr);

    // v-only depthwise 3x3
    dwconv_v_kernel<<<dim3(NB * CIN, HEI / 32), 256>>>(dww);

    // fused q/k dwconv + sumsq + gram
    qk_fused_kernel<<<dim3(256, NB * NHEADS), 256, QK_SMEM_BYTES>>>(dww);

    // softmax + fold projection into per-batch M
    attn_proj_kernel<<<dim3(NHEADS, NB), 256>>>(temp, projw);

    // final: out = M @ v
    gemm_mma_kernel<1><<<dim3(HW / BN, 1, NB), 256, GEMM_SMEM_BYTES>>>(nullptr, nullptr, out);
}

// round 9
// speedup vs baseline: 2.6973x; 2.6973x over previous
#include <cuda_runtime.h>
#include <math.h>
#include <stdint.h>

// Problem constants
#define HEI   256
#define WID   256
#define HW    65536
#define CIN   192
#define C3    576
#define NB    4
#define NHEADS 8
#define HDIM  24

// ---------------- device scratch ----------------
__device__ __align__(256) float g_qkv [(size_t)NB * C3 * HW];
__device__ __align__(256) float g_qkvd[(size_t)NB * C3 * HW];
__device__ __align__(256) float g_gram[NB * NHEADS * HDIM * HDIM];
__device__ __align__(256) float g_sums[NB * 2 * CIN];
__device__ __align__(256) float g_M   [NB * CIN * CIN];

__device__ __forceinline__ uint32_t to_tf32_bits(float x) {
    uint32_t y; asm("cvt.rna.tf32.f32 %0, %1;" : "=r"(y) : "f"(x)); return y;
}

__device__ __forceinline__ void mma_tf32_16x8x8(
    float& c0, float& c1, float& c2, float& c3,
    uint32_t a0, uint32_t a1, uint32_t a2, uint32_t a3,
    uint32_t b0, uint32_t b1)
{
    asm volatile(
        "mma.sync.aligned.m16n8k8.row.col.f32.tf32.tf32.f32 "
        "{%0,%1,%2,%3}, {%4,%5,%6,%7}, {%8,%9}, {%0,%1,%2,%3};"
        : "+f"(c0), "+f"(c1), "+f"(c2), "+f"(c3)
        : "r"(a0), "r"(a1), "r"(a2), "r"(a3), "r"(b0), "r"(b1));
}

// ---------------- zero small accumulators ----------------
__global__ void zero_small_kernel() {
    int i = blockIdx.x * 256 + threadIdx.x;
    if (i < NB * NHEADS * HDIM * HDIM) g_gram[i] = 0.0f;
    if (i < NB * 2 * CIN)              g_sums[i] = 0.0f;
}

// ---------------- tf32 mma.sync GEMM ----------------
// C[M=channels, N=pixels] = A[M,K] @ B[K,N], K=192.
// Block: BM=192, BN=128, BK=32, 256 thr = 8 warps (4M x 2N), warp tile 48x64.
#define BM 192
#define BN 128
#define BK 32
#define AS_STRIDE 36
#define BS_STRIDE 136
#define AS_FLOATS (BM * AS_STRIDE)
#define BS_FLOATS (BK * BS_STRIDE)
#define STAGE_FLOATS (AS_FLOATS + BS_FLOATS)
#define GEMM_SMEM_BYTES (2 * STAGE_FLOATS * 4)   // 90112

template <int MODE>
__global__ void __launch_bounds__(256) gemm_mma_kernel(
    const float* __restrict__ xin, const float* __restrict__ win, float* __restrict__ outp)
{
    extern __shared__ float smem[];
    const int tid  = threadIdx.x;
    const int b    = blockIdx.z;
    const int pix0 = blockIdx.x * BN;

    const float* Ag; const float* Bg; float* Cg;
    if (MODE == 0) {
        const int m0 = blockIdx.y * BM;
        Ag = win + (size_t)m0 * CIN;
        Bg = xin + (size_t)b * CIN * HW;
        Cg = g_qkv + ((size_t)b * C3 + m0) * HW;
    } else {
        Ag = g_M + (size_t)b * CIN * CIN;
        Bg = g_qkvd + ((size_t)b * C3 + 2 * CIN) * HW;
        Cg = outp + (size_t)b * CIN * HW;
    }

    const int warp  = tid >> 5;
    const int lane  = tid & 31;
    const int warpM = warp >> 1;
    const int warpN = warp & 1;
    const int m0w   = warpM * 48;
    const int n0w   = warpN * 64;
    const int g     = lane >> 2;
    const int cq    = lane & 3;

    const int a_row = tid >> 3;
    const int a_kq  = (tid & 7) * 4;
    const int b_kr  = tid >> 5;
    const int b_n4  = lane * 4;

    float4 areg[6], breg[4];

    auto loadA = [&](int t) {
#pragma unroll
        for (int i = 0; i < 6; i++)
            areg[i] = *(const float4*)&Ag[(size_t)(a_row + i * 32) * CIN + t * BK + a_kq];
    };
    auto loadB = [&](int t) {
#pragma unroll
        for (int i = 0; i < 4; i++)
            breg[i] = *(const float4*)&Bg[(size_t)(t * BK + b_kr + i * 8) * HW + pix0 + b_n4];
    };
    auto storeA = [&](int s) {
        float* As = smem + s * STAGE_FLOATS;
#pragma unroll
        for (int i = 0; i < 6; i++) {
            uint32_t* p = (uint32_t*)&As[(a_row + i * 32) * AS_STRIDE + a_kq];
            p[0] = to_tf32_bits(areg[i].x); p[1] = to_tf32_bits(areg[i].y);
            p[2] = to_tf32_bits(areg[i].z); p[3] = to_tf32_bits(areg[i].w);
        }
    };
    auto storeB = [&](int s) {
        float* Bs = smem + s * STAGE_FLOATS + AS_FLOATS;
#pragma unroll
        for (int i = 0; i < 4; i++) {
            uint32_t* p = (uint32_t*)&Bs[(b_kr + i * 8) * BS_STRIDE + b_n4];
            p[0] = to_tf32_bits(breg[i].x); p[1] = to_tf32_bits(breg[i].y);
            p[2] = to_tf32_bits(breg[i].z); p[3] = to_tf32_bits(breg[i].w);
        }
    };

    float c[3][8][4];
#pragma unroll
    for (int i = 0; i < 3; i++)
#pragma unroll
        for (int j = 0; j < 8; j++)
#pragma unroll
            for (int q = 0; q < 4; q++) c[i][j][q] = 0.0f;

    loadA(0); loadB(0);
    storeA(0); storeB(0);
    __syncthreads();

#pragma unroll 1
    for (int t = 0; t < 6; t++) {
        if (t < 5) { loadA(t + 1); loadB(t + 1); }
        const int s = t & 1;
        const uint32_t* As = (const uint32_t*)(smem + s * STAGE_FLOATS);
        const uint32_t* Bs = (const uint32_t*)(smem + s * STAGE_FLOATS + AS_FLOATS);
#pragma unroll
        for (int kk = 0; kk < 4; kk++) {
            const int kb = kk * 8;
            uint32_t af[3][4], bf[8][2];
#pragma unroll
            for (int ms = 0; ms < 3; ms++) {
                const int mrow = m0w + ms * 16 + g;
                af[ms][0] = As[(mrow)     * AS_STRIDE + kb + cq];
                af[ms][1] = As[(mrow + 8) * AS_STRIDE + kb + cq];
                af[ms][2] = As[(mrow)     * AS_STRIDE + kb + cq + 4];
                af[ms][3] = As[(mrow + 8) * AS_STRIDE + kb + cq + 4];
            }
#pragma unroll
            for (int ns = 0; ns < 8; ns++) {
                const int ncol = n0w + ns * 8 + g;
                bf[ns][0] = Bs[(kb + cq)     * BS_STRIDE + ncol];
                bf[ns][1] = Bs[(kb + cq + 4) * BS_STRIDE + ncol];
            }
#pragma unroll
            for (int ms = 0; ms < 3; ms++)
#pragma unroll
                for (int ns = 0; ns < 8; ns++)
                    mma_tf32_16x8x8(c[ms][ns][0], c[ms][ns][1], c[ms][ns][2], c[ms][ns][3],
                                    af[ms][0], af[ms][1], af[ms][2], af[ms][3],
                                    bf[ns][0], bf[ns][1]);
        }
        if (t < 5) {
            storeA((t + 1) & 1); storeB((t + 1) & 1);
            __syncthreads();
        }
    }

#pragma unroll
    for (int ms = 0; ms < 3; ms++) {
        const int m = m0w + ms * 16 + g;
#pragma unroll
        for (int ns = 0; ns < 8; ns++) {
            const int n = pix0 + n0w + ns * 8 + cq * 2;
            *(float2*)&Cg[(size_t)m * HW + n]       = make_float2(c[ms][ns][0], c[ms][ns][1]);
            *(float2*)&Cg[(size_t)(m + 8) * HW + n] = make_float2(c[ms][ns][2], c[ms][ns][3]);
        }
    }
}

// ---------------- depthwise 3x3 + fused per-channel sumsq ----------------
__global__ void __launch_bounds__(256) dwconv3x3_kernel(const float* __restrict__ w)
{
    const int bc = blockIdx.x;
    const int ch = bc % C3;
    const int b  = bc / C3;
    const float* ip = g_qkv  + (size_t)bc * HW;
    float*       op = g_qkvd + (size_t)bc * HW;

    __shared__ float s[34][258];
    const int tid = threadIdx.x;
    const int y0  = blockIdx.y * 32;

    for (int i = tid; i < 34 * 256; i += 256) {
        const int r = i >> 8, xc = i & 255;
        const int y = y0 + r - 1;
        s[r][xc + 1] = (y >= 0 && y < HEI) ? ip[y * WID + xc] : 0.0f;
    }
    if (tid < 34) { s[tid][0] = 0.0f; s[tid][257] = 0.0f; }

    float wr[9];
#pragma unroll
    for (int i = 0; i < 9; i++) wr[i] = w[ch * 9 + i];
    __syncthreads();

    float ssq = 0.0f;
#pragma unroll 4
    for (int r = 0; r < 32; r++) {
        float acc = 0.0f;
#pragma unroll
        for (int dy = 0; dy < 3; dy++)
#pragma unroll
            for (int dx = 0; dx < 3; dx++)
                acc = fmaf(s[r + dy][tid + dx], wr[dy * 3 + dx], acc);
        op[(y0 + r) * WID + tid] = acc;
        ssq = fmaf(acc, acc, ssq);
    }

    if (ch < 2 * CIN) {
        __shared__ float red[8];
        const int lane = tid & 31, wp = tid >> 5;
#pragma unroll
        for (int o = 16; o; o >>= 1) ssq += __shfl_down_sync(0xffffffffu, ssq, o);
        if (lane == 0) red[wp] = ssq;
        __syncthreads();
        if (tid == 0) {
            float t = 0.0f;
#pragma unroll
            for (int i = 0; i < 8; i++) t += red[i];
            atomicAdd(&g_sums[b * 2 * CIN + ch], t);
        }
    }
}

// ---------------- tensor-core gram with 3xTF32 ----------------
// G[b,h,:,:] (24x24) += q[24, px] @ k[24, px]^T over this block's pixel chunk.
#define GP      32          // pixel chunks per (b,h)
#define GPX     (HW / GP)   // 2048 pixels per block
#define GSUB    256         // pixels per SMEM subtile
#define QS_ROWS 32          // padded to 32 rows (rows 24-31 zero)
#define GS_STRIDE 260       // floats; 260 % 32 == 4 -> conflict-free frag LDS
#define GQ_FLOATS (QS_ROWS * GS_STRIDE)
#define GK_FLOATS (HDIM * GS_STRIDE)
#define GRED_FLOATS (8 * HDIM * HDIM)
#define GRAM_SMEM_BYTES ((GQ_FLOATS + GK_FLOATS + GRED_FLOATS) * 4)

__global__ void __launch_bounds__(256) gram_tc_kernel()
{
    extern __shared__ float sm[];
    float* qs  = sm;                         // [32][260]
    float* ks  = sm + GQ_FLOATS;             // [24][260]
    float* red = sm + GQ_FLOATS + GK_FLOATS; // [8][576]

    const int bh = blockIdx.y;
    const int b = bh >> 3, h = bh & 7;
    const int px_base = blockIdx.x * GPX;
    const float* qb = g_qkvd + ((size_t)b * C3 + h * HDIM) * HW;
    const float* kb = qb + (size_t)CIN * HW;

    const int tid  = threadIdx.x;
    const int warp = tid >> 5;
    const int lane = tid & 31;
    const int g    = lane >> 2;
    const int cq   = lane & 3;

    // zero pad rows 24..31 of qs
    for (int i = tid; i < 8 * GS_STRIDE; i += 256) qs[24 * GS_STRIDE + i] = 0.0f;

    float c[2][3][4];
#pragma unroll
    for (int mt = 0; mt < 2; mt++)
#pragma unroll
        for (int nt = 0; nt < 3; nt++)
#pragma unroll
            for (int q = 0; q < 4; q++) c[mt][nt][q] = 0.0f;

#pragma unroll 1
    for (int it = 0; it < GPX / GSUB; it++) {
        const int px0 = px_base + it * GSUB;
        __syncthreads();
        for (int i = tid; i < HDIM * (GSUB / 4); i += 256) {
            const int row = i >> 6, c4 = i & 63;
            *(float4*)&qs[row * GS_STRIDE + c4 * 4] = *(const float4*)&qb[(size_t)row * HW + px0 + c4 * 4];
            *(float4*)&ks[row * GS_STRIDE + c4 * 4] = *(const float4*)&kb[(size_t)row * HW + px0 + c4 * 4];
        }
        __syncthreads();

#pragma unroll
        for (int k8 = 0; k8 < 4; k8++) {
            const int kb8 = warp * 32 + k8 * 8;
            uint32_t ah[2][4], al[2][4], bh2[3][2], bl[3][2];
#pragma unroll
            for (int mt = 0; mt < 2; mt++) {
                const int r0 = mt * 16 + g;
#pragma unroll
                for (int q = 0; q < 4; q++) {
                    const int rr = r0 + (q & 1) * 8;
                    const int cc = kb8 + cq + (q >> 1) * 4;
                    const float v = qs[rr * GS_STRIDE + cc];
                    ah[mt][q] = to_tf32_bits(v);
                    al[mt][q] = to_tf32_bits(v - __uint_as_float(ah[mt][q]));
                }
            }
#pragma unroll
            for (int nt = 0; nt < 3; nt++) {
                const int er = nt * 8 + g;
#pragma unroll
                for (int q = 0; q < 2; q++) {
                    const float v = ks[er * GS_STRIDE + kb8 + cq + q * 4];
                    bh2[nt][q] = to_tf32_bits(v);
                    bl[nt][q]  = to_tf32_bits(v - __uint_as_float(bh2[nt][q]));
                }
            }
#pragma unroll
            for (int mt = 0; mt < 2; mt++)
#pragma unroll
                for (int nt = 0; nt < 3; nt++) {
                    mma_tf32_16x8x8(c[mt][nt][0], c[mt][nt][1], c[mt][nt][2], c[mt][nt][3],
                                    ah[mt][0], ah[mt][1], ah[mt][2], ah[mt][3],
                                    bh2[nt][0], bh2[nt][1]);
                    mma_tf32_16x8x8(c[mt][nt][0], c[mt][nt][1], c[mt][nt][2], c[mt][nt][3],
                                    ah[mt][0], ah[mt][1], ah[mt][2], ah[mt][3],
                                    bl[nt][0], bl[nt][1]);
                    mma_tf32_16x8x8(c[mt][nt][0], c[mt][nt][1], c[mt][nt][2], c[mt][nt][3],
                                    al[mt][0], al[mt][1], al[mt][2], al[mt][3],
                                    bh2[nt][0], bh2[nt][1]);
                }
        }
    }

    __syncthreads();
    float* rw = red + warp * (HDIM * HDIM);
#pragma unroll
    for (int mt = 0; mt < 2; mt++) {
        const int d = mt * 16 + g;
#pragma unroll
        for (int nt = 0; nt < 3; nt++) {
            const int e = nt * 8 + cq * 2;
            rw[d * HDIM + e]     = c[mt][nt][0];
            rw[d * HDIM + e + 1] = c[mt][nt][1];
            if (d + 8 < HDIM) {
                rw[(d + 8) * HDIM + e]     = c[mt][nt][2];
                rw[(d + 8) * HDIM + e + 1] = c[mt][nt][3];
            }
        }
    }
    __syncthreads();
    for (int i = tid; i < HDIM * HDIM; i += 256) {
        float s = 0.0f;
#pragma unroll
        for (int w2 = 0; w2 < 8; w2++) s += red[w2 * (HDIM * HDIM) + i];
        atomicAdd(&g_gram[bh * HDIM * HDIM + i], s);
    }
}

// ---------------- softmax + fold projection: M = proj * blockdiag(attn) ----------------
__global__ void __launch_bounds__(256) attn_proj_kernel(
    const float* __restrict__ temp, const float* __restrict__ projw)
{
    const int h = blockIdx.x, b = blockIdx.y;
    __shared__ float attn[HDIM][HDIM];
    __shared__ float nq[HDIM], nk[HDIM];
    const int tid = threadIdx.x;

    if (tid < HDIM) {
        nq[tid] = fmaxf(sqrtf(g_sums[b * 2 * CIN + h * HDIM + tid]), 1e-12f);
        nk[tid] = fmaxf(sqrtf(g_sums[b * 2 * CIN + CIN + h * HDIM + tid]), 1e-12f);
    }
    __syncthreads();

    if (tid < HDIM) {
        const float t = temp[h];
        const float* gg = g_gram + ((b * NHEADS + h) * HDIM + tid) * HDIM;
        float row[HDIM];
        float mx = -1e30f;
        const float inq = 1.0f / nq[tid];
#pragma unroll
        for (int e = 0; e < HDIM; e++) {
            row[e] = gg[e] * t * inq / nk[e];
            mx = fmaxf(mx, row[e]);
        }
        float ssum = 0.0f;
#pragma unroll
        for (int e = 0; e < HDIM; e++) { row[e] = expf(row[e] - mx); ssum += row[e]; }
        const float inv = 1.0f / ssum;
#pragma unroll
        for (int e = 0; e < HDIM; e++) attn[tid][e] = row[e] * inv;
    }
    __syncthreads();

    for (int idx = tid; idx < CIN * HDIM; idx += 256) {
        const int o = idx / HDIM, e = idx % HDIM;
        float ssum = 0.0f;
#pragma unroll
        for (int d = 0; d < HDIM; d++)
            ssum = fmaf(projw[o * CIN + h * HDIM + d], attn[d][e], ssum);
        g_M[(size_t)b * CIN * CIN + o * CIN + h * HDIM + e] = ssum;
    }
}

// ---------------- launch ----------------
extern "C" void kernel_launch(void* const* d_in, const int* in_sizes, int n_in,
                              void* d_out, int out_size)
{
    const float *x = nullptr, *qkvw = nullptr, *dww = nullptr, *projw = nullptr, *temp = nullptr;
    for (int i = 0; i < n_in; i++) {
        switch (in_sizes[i]) {
            case NB * CIN * HW:   x     = (const float*)d_in[i]; break;
            case C3 * CIN:        qkvw  = (const float*)d_in[i]; break;
            case C3 * 9:          dww   = (const float*)d_in[i]; break;
            case CIN * CIN:       projw = (const float*)d_in[i]; break;
            case NHEADS:          temp  = (const float*)d_in[i]; break;
        }
    }
    float* out = (float*)d_out;

    static int configured = 0;
    if (!configured) {
        cudaFuncSetAttribute(gemm_mma_kernel<0>, cudaFuncAttributeMaxDynamicSharedMemorySize, GEMM_SMEM_BYTES);
        cudaFuncSetAttribute(gemm_mma_kernel<1>, cudaFuncAttributeMaxDynamicSharedMemorySize, GEMM_SMEM_BYTES);
        cudaFuncSetAttribute(gram_tc_kernel, cudaFuncAttributeMaxDynamicSharedMemorySize, GRAM_SMEM_BYTES);
        configured = 1;
    }

    zero_small_kernel<<<72, 256>>>();

    // qkv 1x1 conv (R3 grid order: pixel tiles fastest)
    gemm_mma_kernel<0><<<dim3(HW / BN, 3, NB), 256, GEMM_SMEM_BYTES>>>(x, qkvw, nullptr);

    // depthwise 3x3 (+ fused q/k sum-of-squares)
    dwconv3x3_kernel<<<dim3(NB * C3, HEI / 32), 256>>>(dww);

    // tensor-core gram (3xTF32)
    gram_tc_kernel<<<dim3(GP, NB * NHEADS), 256, GRAM_SMEM_BYTES>>>();

    // softmax + fold projection into per-batch M
    attn_proj_kernel<<<dim3(NHEADS, NB), 256>>>(temp, projw);

    // final: out = M @ v
    gemm_mma_kernel<1><<<dim3(HW / BN, 1, NB), 256, GEMM_SMEM_BYTES>>>(nullptr, nullptr, out);
}

// round 10
// speedup vs baseline: 2.7970x; 1.0370x over previous
#include <cuda_runtime.h>
#include <math.h>
#include <stdint.h>

// Problem constants
#define HEI   256
#define WID   256
#define HW    65536
#define CIN   192
#define C3    576
#define NB    4
#define NHEADS 8
#define HDIM  24

// ---------------- device scratch ----------------
__device__ __align__(256) float g_qkv [(size_t)NB * C3 * HW];
__device__ __align__(256) float g_qkvd[(size_t)NB * C3 * HW];
__device__ __align__(256) float g_gram[NB * NHEADS * HDIM * HDIM];
__device__ __align__(256) float g_sums[NB * 2 * CIN];
__device__ __align__(256) float g_M   [NB * CIN * CIN];

__device__ __forceinline__ uint32_t to_tf32_bits(float x) {
    uint32_t y; asm("cvt.rna.tf32.f32 %0, %1;" : "=r"(y) : "f"(x)); return y;
}
__device__ __forceinline__ uint32_t smem_u32(const void* p) {
    uint32_t a;
    asm("{ .reg .u64 t; cvta.to.shared.u64 t, %1; cvt.u32.u64 %0, t; }" : "=r"(a) : "l"(p));
    return a;
}
__device__ __forceinline__ void cp_async16(uint32_t saddr, const void* gaddr) {
    asm volatile("cp.async.ca.shared.global [%0], [%1], 16;" :: "r"(saddr), "l"(gaddr));
}
#define CP_COMMIT() asm volatile("cp.async.commit_group;" ::: "memory")
#define CP_WAIT1()  asm volatile("cp.async.wait_group 1;" ::: "memory")
#define CP_WAIT0()  asm volatile("cp.async.wait_group 0;" ::: "memory")

__device__ __forceinline__ void mma_tf32_16x8x8(
    float& c0, float& c1, float& c2, float& c3,
    uint32_t a0, uint32_t a1, uint32_t a2, uint32_t a3,
    uint32_t b0, uint32_t b1)
{
    asm volatile(
        "mma.sync.aligned.m16n8k8.row.col.f32.tf32.tf32.f32 "
        "{%0,%1,%2,%3}, {%4,%5,%6,%7}, {%8,%9}, {%0,%1,%2,%3};"
        : "+f"(c0), "+f"(c1), "+f"(c2), "+f"(c3)
        : "r"(a0), "r"(a1), "r"(a2), "r"(a3), "r"(b0), "r"(b1));
}

// ---------------- zero small accumulators ----------------
__global__ void zero_small_kernel() {
    int i = blockIdx.x * 256 + threadIdx.x;
    if (i < NB * NHEADS * HDIM * HDIM) g_gram[i] = 0.0f;
    if (i < NB * 2 * CIN)              g_sums[i] = 0.0f;
}

// ---------------- tf32 mma.sync GEMM ----------------
// C[M=channels, N=pixels] = A[M,K] @ B[K,N], K=192.
// Block: BM=192, BN=128, BK=32, 256 thr = 8 warps (4M x 2N), warp tile 48x64.
// MODE 0 loops the 3 channel-tiles inside the block so x is read from DRAM once
// (tiles 2,3 hit L2); MODE 1 has a single m-tile.
#define BM 192
#define BN 128
#define BK 32
#define AS_STRIDE 36
#define BS_STRIDE 136
#define AS_FLOATS (BM * AS_STRIDE)
#define BS_FLOATS (BK * BS_STRIDE)
#define STAGE_FLOATS (AS_FLOATS + BS_FLOATS)
#define GEMM_SMEM_BYTES (2 * STAGE_FLOATS * 4)   // 90112

template <int MODE>
__global__ void __launch_bounds__(256) gemm_mma_kernel(
    const float* __restrict__ xin, const float* __restrict__ win, float* __restrict__ outp)
{
    extern __shared__ float smem[];
    const int tid  = threadIdx.x;
    const int b    = blockIdx.z;
    const int pix0 = blockIdx.x * BN;
    const int NMT  = (MODE == 0) ? 3 : 1;

    const float* Bg;
    if (MODE == 0) Bg = xin + (size_t)b * CIN * HW;
    else           Bg = g_qkvd + ((size_t)b * C3 + 2 * CIN) * HW;

    const int warp  = tid >> 5;
    const int lane  = tid & 31;
    const int warpM = warp >> 1;
    const int warpN = warp & 1;
    const int m0w   = warpM * 48;
    const int n0w   = warpN * 64;
    const int g     = lane >> 2;
    const int cq    = lane & 3;

    const int a_row = tid >> 3;
    const int a_kq  = (tid & 7) * 4;
    const int b_kr  = tid >> 5;
    const int b_n4  = lane * 4;

    const float* Ag; float* Cg;
    float4 areg[6], breg[4];

    auto loadA = [&](int t) {
#pragma unroll
        for (int i = 0; i < 6; i++)
            areg[i] = *(const float4*)&Ag[(size_t)(a_row + i * 32) * CIN + t * BK + a_kq];
    };
    auto loadB = [&](int t) {
#pragma unroll
        for (int i = 0; i < 4; i++)
            breg[i] = *(const float4*)&Bg[(size_t)(t * BK + b_kr + i * 8) * HW + pix0 + b_n4];
    };
    auto storeA = [&](int s) {
        float* As = smem + s * STAGE_FLOATS;
#pragma unroll
        for (int i = 0; i < 6; i++) {
            uint32_t* p = (uint32_t*)&As[(a_row + i * 32) * AS_STRIDE + a_kq];
            p[0] = to_tf32_bits(areg[i].x); p[1] = to_tf32_bits(areg[i].y);
            p[2] = to_tf32_bits(areg[i].z); p[3] = to_tf32_bits(areg[i].w);
        }
    };
    auto storeB = [&](int s) {
        float* Bs = smem + s * STAGE_FLOATS + AS_FLOATS;
#pragma unroll
        for (int i = 0; i < 4; i++) {
            uint32_t* p = (uint32_t*)&Bs[(b_kr + i * 8) * BS_STRIDE + b_n4];
            p[0] = to_tf32_bits(breg[i].x); p[1] = to_tf32_bits(breg[i].y);
            p[2] = to_tf32_bits(breg[i].z); p[3] = to_tf32_bits(breg[i].w);
        }
    };

#pragma unroll 1
    for (int mt = 0; mt < NMT; mt++) {
        if (MODE == 0) {
            Ag = win + (size_t)(mt * BM) * CIN;
            Cg = g_qkv + ((size_t)b * C3 + mt * BM) * HW;
        } else {
            Ag = g_M + (size_t)b * CIN * CIN;
            Cg = outp + (size_t)b * CIN * HW;
        }

        float c[3][8][4];
#pragma unroll
        for (int i = 0; i < 3; i++)
#pragma unroll
            for (int j = 0; j < 8; j++)
#pragma unroll
                for (int q = 0; q < 4; q++) c[i][j][q] = 0.0f;

        loadA(0); loadB(0);
        storeA(0); storeB(0);
        __syncthreads();

#pragma unroll 1
        for (int t = 0; t < 6; t++) {
            if (t < 5) { loadA(t + 1); loadB(t + 1); }
            const int s = t & 1;
            const uint32_t* As = (const uint32_t*)(smem + s * STAGE_FLOATS);
            const uint32_t* Bs = (const uint32_t*)(smem + s * STAGE_FLOATS + AS_FLOATS);
#pragma unroll
            for (int kk = 0; kk < 4; kk++) {
                const int kb = kk * 8;
                uint32_t af[3][4], bf[8][2];
#pragma unroll
                for (int ms = 0; ms < 3; ms++) {
                    const int mrow = m0w + ms * 16 + g;
                    af[ms][0] = As[(mrow)     * AS_STRIDE + kb + cq];
                    af[ms][1] = As[(mrow + 8) * AS_STRIDE + kb + cq];
                    af[ms][2] = As[(mrow)     * AS_STRIDE + kb + cq + 4];
                    af[ms][3] = As[(mrow + 8) * AS_STRIDE + kb + cq + 4];
                }
#pragma unroll
                for (int ns = 0; ns < 8; ns++) {
                    const int ncol = n0w + ns * 8 + g;
                    bf[ns][0] = Bs[(kb + cq)     * BS_STRIDE + ncol];
                    bf[ns][1] = Bs[(kb + cq + 4) * BS_STRIDE + ncol];
                }
#pragma unroll
                for (int ms = 0; ms < 3; ms++)
#pragma unroll
                    for (int ns = 0; ns < 8; ns++)
                        mma_tf32_16x8x8(c[ms][ns][0], c[ms][ns][1], c[ms][ns][2], c[ms][ns][3],
                                        af[ms][0], af[ms][1], af[ms][2], af[ms][3],
                                        bf[ns][0], bf[ns][1]);
            }
            if (t < 5) {
                storeA((t + 1) & 1); storeB((t + 1) & 1);
                __syncthreads();
            }
        }

#pragma unroll
        for (int ms = 0; ms < 3; ms++) {
            const int m = m0w + ms * 16 + g;
#pragma unroll
            for (int ns = 0; ns < 8; ns++) {
                const int n = pix0 + n0w + ns * 8 + cq * 2;
                *(float2*)&Cg[(size_t)m * HW + n]       = make_float2(c[ms][ns][0], c[ms][ns][1]);
                *(float2*)&Cg[(size_t)(m + 8) * HW + n] = make_float2(c[ms][ns][2], c[ms][ns][3]);
            }
        }
        if (mt + 1 < NMT) __syncthreads();
    }
}

// ---------------- depthwise 3x3 + fused per-channel sumsq ----------------
__global__ void __launch_bounds__(256) dwconv3x3_kernel(const float* __restrict__ w)
{
    const int bc = blockIdx.x;
    const int ch = bc % C3;
    const int b  = bc / C3;
    const float* ip = g_qkv  + (size_t)bc * HW;
    float*       op = g_qkvd + (size_t)bc * HW;

    __shared__ float s[34][258];
    const int tid = threadIdx.x;
    const int y0  = blockIdx.y * 32;

    for (int i = tid; i < 34 * 256; i += 256) {
        const int r = i >> 8, xc = i & 255;
        const int y = y0 + r - 1;
        s[r][xc + 1] = (y >= 0 && y < HEI) ? ip[y * WID + xc] : 0.0f;
    }
    if (tid < 34) { s[tid][0] = 0.0f; s[tid][257] = 0.0f; }

    float wr[9];
#pragma unroll
    for (int i = 0; i < 9; i++) wr[i] = w[ch * 9 + i];
    __syncthreads();

    float ssq = 0.0f;
#pragma unroll 4
    for (int r = 0; r < 32; r++) {
        float acc = 0.0f;
#pragma unroll
        for (int dy = 0; dy < 3; dy++)
#pragma unroll
            for (int dx = 0; dx < 3; dx++)
                acc = fmaf(s[r + dy][tid + dx], wr[dy * 3 + dx], acc);
        op[(y0 + r) * WID + tid] = acc;
        ssq = fmaf(acc, acc, ssq);
    }

    if (ch < 2 * CIN) {
        __shared__ float red[8];
        const int lane = tid & 31, wp = tid >> 5;
#pragma unroll
        for (int o = 16; o; o >>= 1) ssq += __shfl_down_sync(0xffffffffu, ssq, o);
        if (lane == 0) red[wp] = ssq;
        __syncthreads();
        if (tid == 0) {
            float t = 0.0f;
#pragma unroll
            for (int i = 0; i < 8; i++) t += red[i];
            atomicAdd(&g_sums[b * 2 * CIN + ch], t);
        }
    }
}

// ---------------- tensor-core gram with 3xTF32, cp.async double-buffered ----------------
// G[b,h,:,:] (24x24) += q[24, px] @ k[24, px]^T over this block's pixel chunk.
#define GP      32          // pixel chunks per (b,h)
#define GPX     (HW / GP)   // 2048 pixels per block
#define GSUB    128         // pixels per SMEM subtile
#define GNIT    (GPX / GSUB)  // 16 iterations
#define GS_STRIDE 132       // floats; 132 % 32 == 4 -> conflict-free frag LDS
#define GQ_FLOATS (32 * GS_STRIDE)   // rows 24..31 zero pad
#define GK_FLOATS (HDIM * GS_STRIDE)
#define GSTAGE    (GQ_FLOATS + GK_FLOATS)      // 7392 floats
#define GRED_FLOATS (8 * HDIM * HDIM)
#define GRAM_SMEM_BYTES ((2 * GSTAGE + GRED_FLOATS) * 4)   // 77568

__global__ void __launch_bounds__(256) gram_tc_kernel()
{
    extern __shared__ float sm[];
    float* red = sm + 2 * GSTAGE;

    const int bh = blockIdx.y;
    const int b = bh >> 3, h = bh & 7;
    const int px_base = blockIdx.x * GPX;
    const float* qb = g_qkvd + ((size_t)b * C3 + h * HDIM) * HW;
    const float* kb = qb + (size_t)CIN * HW;

    const int tid  = threadIdx.x;
    const int warp = tid >> 5;
    const int lane = tid & 31;
    const int g    = lane >> 2;
    const int cq   = lane & 3;

    const uint32_t smb = smem_u32(sm);

    // zero pad rows 24..31 of qs in BOTH stages
    for (int i = tid; i < 8 * GS_STRIDE; i += 256) {
        sm[24 * GS_STRIDE + i] = 0.0f;
        sm[GSTAGE + 24 * GS_STRIDE + i] = 0.0f;
    }

    // per-thread copy mapping: 1536 float4 per stage, 6 per thread
    auto issue_stage = [&](int it, int s) {
        const int px0 = px_base + it * GSUB;
        const uint32_t sb = smb + (uint32_t)(s * GSTAGE) * 4u;
#pragma unroll
        for (int j = 0; j < 6; j++) {
            const int idx = tid + j * 256;
            const int row48 = idx >> 5;         // 0..47
            const int c4    = idx & 31;
            const int r     = (row48 < HDIM) ? row48 : row48 - HDIM;
            const float* src = ((row48 < HDIM) ? qb : kb) + (size_t)r * HW + px0 + c4 * 4;
            const uint32_t dst = sb + (uint32_t)(((row48 < HDIM) ? r * GS_STRIDE
                                     : GQ_FLOATS + r * GS_STRIDE) + c4 * 4) * 4u;
            cp_async16(dst, src);
        }
    };

    float c[2][3][4];
#pragma unroll
    for (int mt = 0; mt < 2; mt++)
#pragma unroll
        for (int nt = 0; nt < 3; nt++)
#pragma unroll
            for (int q = 0; q < 4; q++) c[mt][nt][q] = 0.0f;

    issue_stage(0, 0);
    CP_COMMIT();

#pragma unroll 1
    for (int it = 0; it < GNIT; it++) {
        if (it + 1 < GNIT) {
            issue_stage(it + 1, (it + 1) & 1);
            CP_COMMIT();
            CP_WAIT1();
        } else {
            CP_WAIT0();
        }
        __syncthreads();

        const float* qs = sm + (it & 1) * GSTAGE;
        const float* ks = qs + GQ_FLOATS;

        // warp covers pixel window [warp*16, warp*16+16): 2 k8 steps
#pragma unroll
        for (int k8 = 0; k8 < 2; k8++) {
            const int kb8 = warp * 16 + k8 * 8;
            uint32_t ah[2][4], al[2][4], bh2[3][2], bl[3][2];
#pragma unroll
            for (int mt = 0; mt < 2; mt++) {
                const int r0 = mt * 16 + g;
#pragma unroll
                for (int q = 0; q < 4; q++) {
                    const int rr = r0 + (q & 1) * 8;
                    const int cc = kb8 + cq + (q >> 1) * 4;
                    const float v = qs[rr * GS_STRIDE + cc];
                    ah[mt][q] = to_tf32_bits(v);
                    al[mt][q] = to_tf32_bits(v - __uint_as_float(ah[mt][q]));
                }
            }
#pragma unroll
            for (int nt = 0; nt < 3; nt++) {
                const int er = nt * 8 + g;
#pragma unroll
                for (int q = 0; q < 2; q++) {
                    const float v = ks[er * GS_STRIDE + kb8 + cq + q * 4];
                    bh2[nt][q] = to_tf32_bits(v);
                    bl[nt][q]  = to_tf32_bits(v - __uint_as_float(bh2[nt][q]));
                }
            }
#pragma unroll
            for (int mt = 0; mt < 2; mt++)
#pragma unroll
                for (int nt = 0; nt < 3; nt++) {
                    mma_tf32_16x8x8(c[mt][nt][0], c[mt][nt][1], c[mt][nt][2], c[mt][nt][3],
                                    ah[mt][0], ah[mt][1], ah[mt][2], ah[mt][3],
                                    bh2[nt][0], bh2[nt][1]);
                    mma_tf32_16x8x8(c[mt][nt][0], c[mt][nt][1], c[mt][nt][2], c[mt][nt][3],
                                    ah[mt][0], ah[mt][1], ah[mt][2], ah[mt][3],
                                    bl[nt][0], bl[nt][1]);
                    mma_tf32_16x8x8(c[mt][nt][0], c[mt][nt][1], c[mt][nt][2], c[mt][nt][3],
                                    al[mt][0], al[mt][1], al[mt][2], al[mt][3],
                                    bh2[nt][0], bh2[nt][1]);
                }
        }
        __syncthreads();
    }

    float* rw = red + warp * (HDIM * HDIM);
#pragma unroll
    for (int mt = 0; mt < 2; mt++) {
        const int d = mt * 16 + g;
#pragma unroll
        for (int nt = 0; nt < 3; nt++) {
            const int e = nt * 8 + cq * 2;
            rw[d * HDIM + e]     = c[mt][nt][0];
            rw[d * HDIM + e + 1] = c[mt][nt][1];
            if (d + 8 < HDIM) {
                rw[(d + 8) * HDIM + e]     = c[mt][nt][2];
                rw[(d + 8) * HDIM + e + 1] = c[mt][nt][3];
            }
        }
    }
    __syncthreads();
    for (int i = tid; i < HDIM * HDIM; i += 256) {
        float s = 0.0f;
#pragma unroll
        for (int w2 = 0; w2 < 8; w2++) s += red[w2 * (HDIM * HDIM) + i];
        atomicAdd(&g_gram[bh * HDIM * HDIM + i], s);
    }
}

// ---------------- softmax + fold projection: M = proj * blockdiag(attn) ----------------
__global__ void __launch_bounds__(256) attn_proj_kernel(
    const float* __restrict__ temp, const float* __restrict__ projw)
{
    const int h = blockIdx.x, b = blockIdx.y;
    __shared__ float attn[HDIM][HDIM];
    __shared__ float nq[HDIM], nk[HDIM];
    const int tid = threadIdx.x;

    if (tid < HDIM) {
        nq[tid] = fmaxf(sqrtf(g_sums[b * 2 * CIN + h * HDIM + tid]), 1e-12f);
        nk[tid] = fmaxf(sqrtf(g_sums[b * 2 * CIN + CIN + h * HDIM + tid]), 1e-12f);
    }
    __syncthreads();

    if (tid < HDIM) {
        const float t = temp[h];
        const float* gg = g_gram + ((b * NHEADS + h) * HDIM + tid) * HDIM;
        float row[HDIM];
        float mx = -1e30f;
        const float inq = 1.0f / nq[tid];
#pragma unroll
        for (int e = 0; e < HDIM; e++) {
            row[e] = gg[e] * t * inq / nk[e];
            mx = fmaxf(mx, row[e]);
        }
        float ssum = 0.0f;
#pragma unroll
        for (int e = 0; e < HDIM; e++) { row[e] = expf(row[e] - mx); ssum += row[e]; }
        const float inv = 1.0f / ssum;
#pragma unroll
        for (int e = 0; e < HDIM; e++) attn[tid][e] = row[e] * inv;
    }
    __syncthreads();

    for (int idx = tid; idx < CIN * HDIM; idx += 256) {
        const int o = idx / HDIM, e = idx % HDIM;
        float ssum = 0.0f;
#pragma unroll
        for (int d = 0; d < HDIM; d++)
            ssum = fmaf(projw[o * CIN + h * HDIM + d], attn[d][e], ssum);
        g_M[(size_t)b * CIN * CIN + o * CIN + h * HDIM + e] = ssum;
    }
}

// ---------------- launch ----------------
extern "C" void kernel_launch(void* const* d_in, const int* in_sizes, int n_in,
                              void* d_out, int out_size)
{
    const float *x = nullptr, *qkvw = nullptr, *dww = nullptr, *projw = nullptr, *temp = nullptr;
    for (int i = 0; i < n_in; i++) {
        switch (in_sizes[i]) {
            case NB * CIN * HW:   x     = (const float*)d_in[i]; break;
            case C3 * CIN:        qkvw  = (const float*)d_in[i]; break;
            case C3 * 9:          dww   = (const float*)d_in[i]; break;
            case CIN * CIN:       projw = (const float*)d_in[i]; break;
            case NHEADS:          temp  = (const float*)d_in[i]; break;
        }
    }
    float* out = (float*)d_out;

    static int configured = 0;
    if (!configured) {
        cudaFuncSetAttribute(gemm_mma_kernel<0>, cudaFuncAttributeMaxDynamicSharedMemorySize, GEMM_SMEM_BYTES);
        cudaFuncSetAttribute(gemm_mma_kernel<1>, cudaFuncAttributeMaxDynamicSharedMemorySize, GEMM_SMEM_BYTES);
        cudaFuncSetAttribute(gram_tc_kernel, cudaFuncAttributeMaxDynamicSharedMemorySize, GRAM_SMEM_BYTES);
        configured = 1;
    }

    zero_small_kernel<<<72, 256>>>();

    // qkv 1x1 conv: all 3 channel tiles inside the block -> x read from DRAM once
    gemm_mma_kernel<0><<<dim3(HW / BN, 1, NB), 256, GEMM_SMEM_BYTES>>>(x, qkvw, nullptr);

    // depthwise 3x3 (+ fused q/k sum-of-squares)
    dwconv3x3_kernel<<<dim3(NB * C3, HEI / 32), 256>>>(dww);

    // tensor-core gram (3xTF32, cp.async pipelined)
    gram_tc_kernel<<<dim3(GP, NB * NHEADS), 256, GRAM_SMEM_BYTES>>>();

    // softmax + fold projection into per-batch M
    attn_proj_kernel<<<dim3(NHEADS, NB), 256>>>(temp, projw);

    // final: out = M @ v
    gemm_mma_kernel<1><<<dim3(HW / BN, 1, NB), 256, GEMM_SMEM_BYTES>>>(nullptr, nullptr, out);
}

// round 11
// speedup vs baseline: 3.4169x; 1.2216x over previous
#include <cuda_runtime.h>
#include <cuda_fp16.h>
#include <math.h>
#include <stdint.h>

// Problem constants
#define HEI   256
#define WID   256
#define HW    65536
#define CIN   192
#define C3    576
#define NB    4
#define NHEADS 8
#define HDIM  24

// ---------------- device scratch ----------------
__device__ __align__(256) float g_qkv [(size_t)NB * C3 * HW];
__device__ __align__(256) float g_qkvd[(size_t)NB * C3 * HW];
__device__ __align__(256) float g_gram[NB * NHEADS * HDIM * HDIM];
__device__ __align__(256) float g_sums[NB * 2 * CIN];
__device__ __align__(256) float g_M   [NB * CIN * CIN];

__device__ __forceinline__ uint32_t to_tf32_bits(float x) {
    uint32_t y; asm("cvt.rna.tf32.f32 %0, %1;" : "=r"(y) : "f"(x)); return y;
}
__device__ __forceinline__ uint32_t smem_u32(const void* p) {
    uint32_t a;
    asm("{ .reg .u64 t; cvta.to.shared.u64 t, %1; cvt.u32.u64 %0, t; }" : "=r"(a) : "l"(p));
    return a;
}
__device__ __forceinline__ void cp_async16(uint32_t saddr, const void* gaddr) {
    asm volatile("cp.async.ca.shared.global [%0], [%1], 16;" :: "r"(saddr), "l"(gaddr));
}
#define CP_COMMIT() asm volatile("cp.async.commit_group;" ::: "memory")
#define CP_WAIT1()  asm volatile("cp.async.wait_group 1;" ::: "memory")
#define CP_WAIT0()  asm volatile("cp.async.wait_group 0;" ::: "memory")

__device__ __forceinline__ uint32_t pack_h2(float lo, float hi) {
    __half2 h = __floats2half2_rn(lo, hi);
    return *reinterpret_cast<uint32_t*>(&h);
}

// fp16 mma, k16, fp32 accumulate
__device__ __forceinline__ void mma_f16_16x8x16(
    float& c0, float& c1, float& c2, float& c3,
    uint32_t a0, uint32_t a1, uint32_t a2, uint32_t a3,
    uint32_t b0, uint32_t b1)
{
    asm volatile(
        "mma.sync.aligned.m16n8k16.row.col.f32.f16.f16.f32 "
        "{%0,%1,%2,%3}, {%4,%5,%6,%7}, {%8,%9}, {%0,%1,%2,%3};"
        : "+f"(c0), "+f"(c1), "+f"(c2), "+f"(c3)
        : "r"(a0), "r"(a1), "r"(a2), "r"(a3), "r"(b0), "r"(b1));
}

// tf32 mma (still used by gram 3xTF32 path)
__device__ __forceinline__ void mma_tf32_16x8x8(
    float& c0, float& c1, float& c2, float& c3,
    uint32_t a0, uint32_t a1, uint32_t a2, uint32_t a3,
    uint32_t b0, uint32_t b1)
{
    asm volatile(
        "mma.sync.aligned.m16n8k8.row.col.f32.tf32.tf32.f32 "
        "{%0,%1,%2,%3}, {%4,%5,%6,%7}, {%8,%9}, {%0,%1,%2,%3};"
        : "+f"(c0), "+f"(c1), "+f"(c2), "+f"(c3)
        : "r"(a0), "r"(a1), "r"(a2), "r"(a3), "r"(b0), "r"(b1));
}

// ---------------- zero small accumulators ----------------
__global__ void zero_small_kernel() {
    int i = blockIdx.x * 256 + threadIdx.x;
    if (i < NB * NHEADS * HDIM * HDIM) g_gram[i] = 0.0f;
    if (i < NB * 2 * CIN)              g_sums[i] = 0.0f;
}

// ---------------- fp16 mma.sync GEMM ----------------
// C[M=channels, N=pixels] = A[M,K] @ B[K,N], K=192, fp32 accum.
// Block: BM=192, BN=128, BK=32, 256 thr = 8 warps (4M x 2N), warp tile 48x64.
// A smem: halves, row stride 40 (u32 stride 20 -> conflict-free frags).
// B smem: k-pair-packed u32 rows [kp][n], stride 136 u32 -> conflict-free frags.
#define BM 192
#define BN 128
#define BK 32
#define SA_U32   20                  // u32 per A row (32 halves + 8 pad)
#define AS_U32   (BM * SA_U32)       // 3840
#define SBU      136                 // u32 per kp row (128 + 8 pad)
#define BS_U32   (16 * SBU)          // 2176
#define STAGE_U32 (AS_U32 + BS_U32)  // 6016
#define GEMM_SMEM_BYTES (2 * STAGE_U32 * 4)   // 48128

template <int MODE>
__global__ void __launch_bounds__(256) gemm_mma_kernel(
    const float* __restrict__ xin, const float* __restrict__ win, float* __restrict__ outp)
{
    extern __shared__ uint32_t smem32[];
    const int tid  = threadIdx.x;
    const int b    = blockIdx.z;
    const int pix0 = blockIdx.x * BN;
    const int NMT  = (MODE == 0) ? 3 : 1;

    const float* Bg;
    if (MODE == 0) Bg = xin + (size_t)b * CIN * HW;
    else           Bg = g_qkvd + ((size_t)b * C3 + 2 * CIN) * HW;

    const int warp  = tid >> 5;
    const int lane  = tid & 31;
    const int warpM = warp >> 1;
    const int warpN = warp & 1;
    const int m0w   = warpM * 48;
    const int n0w   = warpN * 64;
    const int g     = lane >> 2;
    const int cq    = lane & 3;

    const int a_row = tid >> 3;              // 0..31 (+i*32)
    const int a_kq  = (tid & 7) * 4;         // 0,4,...,28
    const int b_kp  = tid >> 5;              // 0..7 (+i*8)
    const int b_px  = lane * 4;

    const float* Ag; float* Cg;
    float4 areg[6], brege[2], brego[2];

    auto loadA = [&](int t) {
#pragma unroll
        for (int i = 0; i < 6; i++)
            areg[i] = *(const float4*)&Ag[(size_t)(a_row + i * 32) * CIN + t * BK + a_kq];
    };
    auto loadB = [&](int t) {
#pragma unroll
        for (int i = 0; i < 2; i++) {
            const float* src = Bg + (size_t)(t * BK + 2 * (b_kp + i * 8)) * HW + pix0 + b_px;
            brege[i] = *(const float4*)src;
            brego[i] = *(const float4*)(src + HW);
        }
    };
    auto storeA = [&](int s) {
        uint32_t* A32 = smem32 + s * STAGE_U32;
#pragma unroll
        for (int i = 0; i < 6; i++) {
            const int base = (a_row + i * 32) * SA_U32 + (tid & 7) * 2;
            uint2 v = make_uint2(pack_h2(areg[i].x, areg[i].y),
                                 pack_h2(areg[i].z, areg[i].w));
            *(uint2*)&A32[base] = v;
        }
    };
    auto storeB = [&](int s) {
        uint32_t* B32 = smem32 + s * STAGE_U32 + AS_U32;
#pragma unroll
        for (int i = 0; i < 2; i++) {
            uint4 v;
            v.x = pack_h2(brege[i].x, brego[i].x);
            v.y = pack_h2(brege[i].y, brego[i].y);
            v.z = pack_h2(brege[i].z, brego[i].z);
            v.w = pack_h2(brege[i].w, brego[i].w);
            *(uint4*)&B32[(b_kp + i * 8) * SBU + b_px] = v;
        }
    };

#pragma unroll 1
    for (int mt = 0; mt < NMT; mt++) {
        if (MODE == 0) {
            Ag = win + (size_t)(mt * BM) * CIN;
            Cg = g_qkv + ((size_t)b * C3 + mt * BM) * HW;
        } else {
            Ag = g_M + (size_t)b * CIN * CIN;
            Cg = outp + (size_t)b * CIN * HW;
        }

        float c[3][8][4];
#pragma unroll
        for (int i = 0; i < 3; i++)
#pragma unroll
            for (int j = 0; j < 8; j++)
#pragma unroll
                for (int q = 0; q < 4; q++) c[i][j][q] = 0.0f;

        loadA(0); loadB(0);
        storeA(0); storeB(0);
        __syncthreads();

#pragma unroll 1
        for (int t = 0; t < 6; t++) {
            if (t < 5) { loadA(t + 1); loadB(t + 1); }
            const int s = t & 1;
            const uint32_t* A32 = smem32 + s * STAGE_U32;
            const uint32_t* B32 = smem32 + s * STAGE_U32 + AS_U32;
#pragma unroll
            for (int ks = 0; ks < 2; ks++) {          // two k16 steps per BK=32
                const int abase = ks * 8;             // u32 offset within A row
                uint32_t af[3][4], bf[8][2];
#pragma unroll
                for (int ms = 0; ms < 3; ms++) {
                    const int mrow = m0w + ms * 16 + g;
                    af[ms][0] = A32[(mrow)     * SA_U32 + abase + cq];
                    af[ms][1] = A32[(mrow + 8) * SA_U32 + abase + cq];
                    af[ms][2] = A32[(mrow)     * SA_U32 + abase + 4 + cq];
                    af[ms][3] = A32[(mrow + 8) * SA_U32 + abase + 4 + cq];
                }
#pragma unroll
                for (int ns = 0; ns < 8; ns++) {
                    const int ncol = n0w + ns * 8 + g;
                    bf[ns][0] = B32[(ks * 8 + cq)     * SBU + ncol];
                    bf[ns][1] = B32[(ks * 8 + cq + 4) * SBU + ncol];
                }
#pragma unroll
                for (int ms = 0; ms < 3; ms++)
#pragma unroll
                    for (int ns = 0; ns < 8; ns++)
                        mma_f16_16x8x16(c[ms][ns][0], c[ms][ns][1], c[ms][ns][2], c[ms][ns][3],
                                        af[ms][0], af[ms][1], af[ms][2], af[ms][3],
                                        bf[ns][0], bf[ns][1]);
            }
            if (t < 5) {
                storeA((t + 1) & 1); storeB((t + 1) & 1);
                __syncthreads();
            }
        }

#pragma unroll
        for (int ms = 0; ms < 3; ms++) {
            const int m = m0w + ms * 16 + g;
#pragma unroll
            for (int ns = 0; ns < 8; ns++) {
                const int n = pix0 + n0w + ns * 8 + cq * 2;
                *(float2*)&Cg[(size_t)m * HW + n]       = make_float2(c[ms][ns][0], c[ms][ns][1]);
                *(float2*)&Cg[(size_t)(m + 8) * HW + n] = make_float2(c[ms][ns][2], c[ms][ns][3]);
            }
        }
        if (mt + 1 < NMT) __syncthreads();
    }
}

// ---------------- depthwise 3x3 + fused per-channel sumsq ----------------
__global__ void __launch_bounds__(256) dwconv3x3_kernel(const float* __restrict__ w)
{
    const int bc = blockIdx.x;
    const int ch = bc % C3;
    const int b  = bc / C3;
    const float* ip = g_qkv  + (size_t)bc * HW;
    float*       op = g_qkvd + (size_t)bc * HW;

    __shared__ float s[34][258];
    const int tid = threadIdx.x;
    const int y0  = blockIdx.y * 32;

    for (int i = tid; i < 34 * 256; i += 256) {
        const int r = i >> 8, xc = i & 255;
        const int y = y0 + r - 1;
        s[r][xc + 1] = (y >= 0 && y < HEI) ? ip[y * WID + xc] : 0.0f;
    }
    if (tid < 34) { s[tid][0] = 0.0f; s[tid][257] = 0.0f; }

    float wr[9];
#pragma unroll
    for (int i = 0; i < 9; i++) wr[i] = w[ch * 9 + i];
    __syncthreads();

    float ssq = 0.0f;
#pragma unroll 4
    for (int r = 0; r < 32; r++) {
        float acc = 0.0f;
#pragma unroll
        for (int dy = 0; dy < 3; dy++)
#pragma unroll
            for (int dx = 0; dx < 3; dx++)
                acc = fmaf(s[r + dy][tid + dx], wr[dy * 3 + dx], acc);
        op[(y0 + r) * WID + tid] = acc;
        ssq = fmaf(acc, acc, ssq);
    }

    if (ch < 2 * CIN) {
        __shared__ float red[8];
        const int lane = tid & 31, wp = tid >> 5;
#pragma unroll
        for (int o = 16; o; o >>= 1) ssq += __shfl_down_sync(0xffffffffu, ssq, o);
        if (lane == 0) red[wp] = ssq;
        __syncthreads();
        if (tid == 0) {
            float t = 0.0f;
#pragma unroll
            for (int i = 0; i < 8; i++) t += red[i];
            atomicAdd(&g_sums[b * 2 * CIN + ch], t);
        }
    }
}

// ---------------- tensor-core gram with 3xTF32, cp.async double-buffered ----------------
#define GP      32          // pixel chunks per (b,h)
#define GPX     (HW / GP)   // 2048 pixels per block
#define GSUB    128         // pixels per SMEM subtile
#define GNIT    (GPX / GSUB)  // 16 iterations
#define GS_STRIDE 132       // floats; 132 % 32 == 4 -> conflict-free frag LDS
#define GQ_FLOATS (32 * GS_STRIDE)   // rows 24..31 zero pad
#define GK_FLOATS (HDIM * GS_STRIDE)
#define GSTAGE    (GQ_FLOATS + GK_FLOATS)      // 7392 floats
#define GRED_FLOATS (8 * HDIM * HDIM)
#define GRAM_SMEM_BYTES ((2 * GSTAGE + GRED_FLOATS) * 4)   // 77568

__global__ void __launch_bounds__(256) gram_tc_kernel()
{
    extern __shared__ float sm[];
    float* red = sm + 2 * GSTAGE;

    const int bh = blockIdx.y;
    const int b = bh >> 3, h = bh & 7;
    const int px_base = blockIdx.x * GPX;
    const float* qb = g_qkvd + ((size_t)b * C3 + h * HDIM) * HW;
    const float* kb = qb + (size_t)CIN * HW;

    const int tid  = threadIdx.x;
    const int warp = tid >> 5;
    const int lane = tid & 31;
    const int g    = lane >> 2;
    const int cq   = lane & 3;

    const uint32_t smb = smem_u32(sm);

    for (int i = tid; i < 8 * GS_STRIDE; i += 256) {
        sm[24 * GS_STRIDE + i] = 0.0f;
        sm[GSTAGE + 24 * GS_STRIDE + i] = 0.0f;
    }

    auto issue_stage = [&](int it, int s) {
        const int px0 = px_base + it * GSUB;
        const uint32_t sb = smb + (uint32_t)(s * GSTAGE) * 4u;
#pragma unroll
        for (int j = 0; j < 6; j++) {
            const int idx = tid + j * 256;
            const int row48 = idx >> 5;
            const int c4    = idx & 31;
            const int r     = (row48 < HDIM) ? row48 : row48 - HDIM;
            const float* src = ((row48 < HDIM) ? qb : kb) + (size_t)r * HW + px0 + c4 * 4;
            const uint32_t dst = sb + (uint32_t)(((row48 < HDIM) ? r * GS_STRIDE
                                     : GQ_FLOATS + r * GS_STRIDE) + c4 * 4) * 4u;
            cp_async16(dst, src);
        }
    };

    float c[2][3][4];
#pragma unroll
    for (int mt = 0; mt < 2; mt++)
#pragma unroll
        for (int nt = 0; nt < 3; nt++)
#pragma unroll
            for (int q = 0; q < 4; q++) c[mt][nt][q] = 0.0f;

    issue_stage(0, 0);
    CP_COMMIT();

#pragma unroll 1
    for (int it = 0; it < GNIT; it++) {
        if (it + 1 < GNIT) {
            issue_stage(it + 1, (it + 1) & 1);
            CP_COMMIT();
            CP_WAIT1();
        } else {
            CP_WAIT0();
        }
        __syncthreads();

        const float* qs = sm + (it & 1) * GSTAGE;
        const float* ks = qs + GQ_FLOATS;

#pragma unroll
        for (int k8 = 0; k8 < 2; k8++) {
            const int kb8 = warp * 16 + k8 * 8;
            uint32_t ah[2][4], al[2][4], bh2[3][2], bl[3][2];
#pragma unroll
            for (int mt = 0; mt < 2; mt++) {
                const int r0 = mt * 16 + g;
#pragma unroll
                for (int q = 0; q < 4; q++) {
                    const int rr = r0 + (q & 1) * 8;
                    const int cc = kb8 + cq + (q >> 1) * 4;
                    const float v = qs[rr * GS_STRIDE + cc];
                    ah[mt][q] = to_tf32_bits(v);
                    al[mt][q] = to_tf32_bits(v - __uint_as_float(ah[mt][q]));
                }
            }
#pragma unroll
            for (int nt = 0; nt < 3; nt++) {
                const int er = nt * 8 + g;
#pragma unroll
                for (int q = 0; q < 2; q++) {
                    const float v = ks[er * GS_STRIDE + kb8 + cq + q * 4];
                    bh2[nt][q] = to_tf32_bits(v);
                    bl[nt][q]  = to_tf32_bits(v - __uint_as_float(bh2[nt][q]));
                }
            }
#pragma unroll
            for (int mt = 0; mt < 2; mt++)
#pragma unroll
                for (int nt = 0; nt < 3; nt++) {
                    mma_tf32_16x8x8(c[mt][nt][0], c[mt][nt][1], c[mt][nt][2], c[mt][nt][3],
                                    ah[mt][0], ah[mt][1], ah[mt][2], ah[mt][3],
                                    bh2[nt][0], bh2[nt][1]);
                    mma_tf32_16x8x8(c[mt][nt][0], c[mt][nt][1], c[mt][nt][2], c[mt][nt][3],
                                    ah[mt][0], ah[mt][1], ah[mt][2], ah[mt][3],
                                    bl[nt][0], bl[nt][1]);
                    mma_tf32_16x8x8(c[mt][nt][0], c[mt][nt][1], c[mt][nt][2], c[mt][nt][3],
                                    al[mt][0], al[mt][1], al[mt][2], al[mt][3],
                                    bh2[nt][0], bh2[nt][1]);
                }
        }
        __syncthreads();
    }

    float* rw = red + warp * (HDIM * HDIM);
#pragma unroll
    for (int mt = 0; mt < 2; mt++) {
        const int d = mt * 16 + g;
#pragma unroll
        for (int nt = 0; nt < 3; nt++) {
            const int e = nt * 8 + cq * 2;
            rw[d * HDIM + e]     = c[mt][nt][0];
            rw[d * HDIM + e + 1] = c[mt][nt][1];
            if (d + 8 < HDIM) {
                rw[(d + 8) * HDIM + e]     = c[mt][nt][2];
                rw[(d + 8) * HDIM + e + 1] = c[mt][nt][3];
            }
        }
    }
    __syncthreads();
    for (int i = tid; i < HDIM * HDIM; i += 256) {
        float s = 0.0f;
#pragma unroll
        for (int w2 = 0; w2 < 8; w2++) s += red[w2 * (HDIM * HDIM) + i];
        atomicAdd(&g_gram[bh * HDIM * HDIM + i], s);
    }
}

// ---------------- softmax + fold projection: M = proj * blockdiag(attn) ----------------
__global__ void __launch_bounds__(256) attn_proj_kernel(
    const float* __restrict__ temp, const float* __restrict__ projw)
{
    const int h = blockIdx.x, b = blockIdx.y;
    __shared__ float attn[HDIM][HDIM];
    __shared__ float nq[HDIM], nk[HDIM];
    const int tid = threadIdx.x;

    if (tid < HDIM) {
        nq[tid] = fmaxf(sqrtf(g_sums[b * 2 * CIN + h * HDIM + tid]), 1e-12f);
        nk[tid] = fmaxf(sqrtf(g_sums[b * 2 * CIN + CIN + h * HDIM + tid]), 1e-12f);
    }
    __syncthreads();

    if (tid < HDIM) {
        const float t = temp[h];
        const float* gg = g_gram + ((b * NHEADS + h) * HDIM + tid) * HDIM;
        float row[HDIM];
        float mx = -1e30f;
        const float inq = 1.0f / nq[tid];
#pragma unroll
        for (int e = 0; e < HDIM; e++) {
            row[e] = gg[e] * t * inq / nk[e];
            mx = fmaxf(mx, row[e]);
        }
        float ssum = 0.0f;
#pragma unroll
        for (int e = 0; e < HDIM; e++) { row[e] = expf(row[e] - mx); ssum += row[e]; }
        const float inv = 1.0f / ssum;
#pragma unroll
        for (int e = 0; e < HDIM; e++) attn[tid][e] = row[e] * inv;
    }
    __syncthreads();

    for (int idx = tid; idx < CIN * HDIM; idx += 256) {
        const int o = idx / HDIM, e = idx % HDIM;
        float ssum = 0.0f;
#pragma unroll
        for (int d = 0; d < HDIM; d++)
            ssum = fmaf(projw[o * CIN + h * HDIM + d], attn[d][e], ssum);
        g_M[(size_t)b * CIN * CIN + o * CIN + h * HDIM + e] = ssum;
    }
}

// ---------------- launch ----------------
extern "C" void kernel_launch(void* const* d_in, const int* in_sizes, int n_in,
                              void* d_out, int out_size)
{
    const float *x = nullptr, *qkvw = nullptr, *dww = nullptr, *projw = nullptr, *temp = nullptr;
    for (int i = 0; i < n_in; i++) {
        switch (in_sizes[i]) {
            case NB * CIN * HW:   x     = (const float*)d_in[i]; break;
            case C3 * CIN:        qkvw  = (const float*)d_in[i]; break;
            case C3 * 9:          dww   = (const float*)d_in[i]; break;
            case CIN * CIN:       projw = (const float*)d_in[i]; break;
            case NHEADS:          temp  = (const float*)d_in[i]; break;
        }
    }
    float* out = (float*)d_out;

    static int configured = 0;
    if (!configured) {
        cudaFuncSetAttribute(gemm_mma_kernel<0>, cudaFuncAttributeMaxDynamicSharedMemorySize, GEMM_SMEM_BYTES);
        cudaFuncSetAttribute(gemm_mma_kernel<1>, cudaFuncAttributeMaxDynamicSharedMemorySize, GEMM_SMEM_BYTES);
        cudaFuncSetAttribute(gram_tc_kernel, cudaFuncAttributeMaxDynamicSharedMemorySize, GRAM_SMEM_BYTES);
        configured = 1;
    }

    zero_small_kernel<<<72, 256>>>();

    // qkv 1x1 conv (fp16 mma, 3 channel tiles per block)
    gemm_mma_kernel<0><<<dim3(HW / BN, 1, NB), 256, GEMM_SMEM_BYTES>>>(x, qkvw, nullptr);

    // depthwise 3x3 (+ fused q/k sum-of-squares)
    dwconv3x3_kernel<<<dim3(NB * C3, HEI / 32), 256>>>(dww);

    // tensor-core gram (3xTF32, cp.async pipelined)
    gram_tc_kernel<<<dim3(GP, NB * NHEADS), 256, GRAM_SMEM_BYTES>>>();

    // softmax + fold projection into per-batch M
    attn_proj_kernel<<<dim3(NHEADS, NB), 256>>>(temp, projw);

    // final: out = M @ v (fp16 mma)
    gemm_mma_kernel<1><<<dim3(HW / BN, 1, NB), 256, GEMM_SMEM_BYTES>>>(nullptr, nullptr, out);
}

// round 12
// speedup vs baseline: 3.7261x; 1.0905x over previous
#include <cuda_runtime.h>
#include <cuda_fp16.h>
#include <math.h>
#include <stdint.h>

// Problem constants
#define HEI   256
#define WID   256
#define HW    65536
#define CIN   192
#define C3    576
#define NB    4
#define NHEADS 8
#define HDIM  24

// ---------------- device scratch ----------------
__device__ __align__(256) float  g_qkv [(size_t)NB * C3 * HW];   // fp32, after 1x1 conv
__device__ __align__(256) __half g_qkvh[(size_t)NB * C3 * HW];   // fp16, after dwconv
__device__ __align__(256) float  g_gram[NB * NHEADS * HDIM * HDIM];
__device__ __align__(256) float  g_sums[NB * 2 * CIN];
__device__ __align__(256) float  g_M   [NB * CIN * CIN];

__device__ __forceinline__ uint32_t smem_u32(const void* p) {
    uint32_t a;
    asm("{ .reg .u64 t; cvta.to.shared.u64 t, %1; cvt.u32.u64 %0, t; }" : "=r"(a) : "l"(p));
    return a;
}
__device__ __forceinline__ void cp_async16(uint32_t saddr, const void* gaddr) {
    asm volatile("cp.async.ca.shared.global [%0], [%1], 16;" :: "r"(saddr), "l"(gaddr));
}
#define CP_COMMIT() asm volatile("cp.async.commit_group;" ::: "memory")
#define CP_WAIT1()  asm volatile("cp.async.wait_group 1;" ::: "memory")
#define CP_WAIT0()  asm volatile("cp.async.wait_group 0;" ::: "memory")

__device__ __forceinline__ uint32_t pack_h2(float lo, float hi) {
    __half2 h = __floats2half2_rn(lo, hi);
    return *reinterpret_cast<uint32_t*>(&h);
}

// fp16 mma, k16, fp32 accumulate
__device__ __forceinline__ void mma_f16_16x8x16(
    float& c0, float& c1, float& c2, float& c3,
    uint32_t a0, uint32_t a1, uint32_t a2, uint32_t a3,
    uint32_t b0, uint32_t b1)
{
    asm volatile(
        "mma.sync.aligned.m16n8k16.row.col.f32.f16.f16.f32 "
        "{%0,%1,%2,%3}, {%4,%5,%6,%7}, {%8,%9}, {%0,%1,%2,%3};"
        : "+f"(c0), "+f"(c1), "+f"(c2), "+f"(c3)
        : "r"(a0), "r"(a1), "r"(a2), "r"(a3), "r"(b0), "r"(b1));
}

// ---------------- zero small accumulators ----------------
__global__ void zero_small_kernel() {
    int i = blockIdx.x * 256 + threadIdx.x;
    if (i < NB * NHEADS * HDIM * HDIM) g_gram[i] = 0.0f;
    if (i < NB * 2 * CIN)              g_sums[i] = 0.0f;
}

// ---------------- fp16 mma.sync GEMM ----------------
// C[M=channels, N=pixels] = A[M,K] @ B[K,N], K=192, fp32 accum.
// Block: BM=192, BN=128, BK=32, 256 thr = 8 warps (4M x 2N), warp tile 48x64.
#define BM 192
#define BN 128
#define BK 32
#define SA_U32   20
#define AS_U32   (BM * SA_U32)       // 3840
#define SBU      136
#define BS_U32   (16 * SBU)          // 2176
#define STAGE_U32 (AS_U32 + BS_U32)  // 6016
#define GEMM_SMEM_BYTES (2 * STAGE_U32 * 4)   // 48128

template <int MODE>
__global__ void __launch_bounds__(256) gemm_mma_kernel(
    const float* __restrict__ xin, const float* __restrict__ win, float* __restrict__ outp)
{
    extern __shared__ uint32_t smem32[];
    const int tid  = threadIdx.x;
    const int b    = blockIdx.z;
    const int pix0 = blockIdx.x * BN;
    const int NMT  = (MODE == 0) ? 3 : 1;

    const float*  BgF = nullptr;
    const __half* BgH = nullptr;
    if (MODE == 0) BgF = xin + (size_t)b * CIN * HW;
    else           BgH = g_qkvh + ((size_t)b * C3 + 2 * CIN) * HW;

    const int warp  = tid >> 5;
    const int lane  = tid & 31;
    const int warpM = warp >> 1;
    const int warpN = warp & 1;
    const int m0w   = warpM * 48;
    const int n0w   = warpN * 64;
    const int g     = lane >> 2;
    const int cq    = lane & 3;

    const int a_row = tid >> 3;
    const int a_kq  = (tid & 7) * 4;
    // MODE 0 B-load mapping
    const int b_kp  = tid >> 5;
    const int b_px  = lane * 4;
    // MODE 1 B-load mapping (one pass covers BK=32)
    const int h_rp  = tid >> 4;          // 0..15 k-pairs
    const int h_px  = (tid & 15) * 8;    // 8 pixels

    const float* Ag; float* Cg;
    float4 areg[6], brege[2], brego[2];
    uint4 hbe, hbo;

    auto loadA = [&](int t) {
#pragma unroll
        for (int i = 0; i < 6; i++)
            areg[i] = *(const float4*)&Ag[(size_t)(a_row + i * 32) * CIN + t * BK + a_kq];
    };
    auto loadB = [&](int t) {
        if (MODE == 0) {
#pragma unroll
            for (int i = 0; i < 2; i++) {
                const float* src = BgF + (size_t)(t * BK + 2 * (b_kp + i * 8)) * HW + pix0 + b_px;
                brege[i] = *(const float4*)src;
                brego[i] = *(const float4*)(src + HW);
            }
        } else {
            const __half* src = BgH + (size_t)(t * BK + 2 * h_rp) * HW + pix0 + h_px;
            hbe = *(const uint4*)src;
            hbo = *(const uint4*)(src + HW);
        }
    };
    auto storeA = [&](int s) {
        uint32_t* A32 = smem32 + s * STAGE_U32;
#pragma unroll
        for (int i = 0; i < 6; i++) {
            const int base = (a_row + i * 32) * SA_U32 + (tid & 7) * 2;
            uint2 v = make_uint2(pack_h2(areg[i].x, areg[i].y),
                                 pack_h2(areg[i].z, areg[i].w));
            *(uint2*)&A32[base] = v;
        }
    };
    auto storeB = [&](int s) {
        uint32_t* B32 = smem32 + s * STAGE_U32 + AS_U32;
        if (MODE == 0) {
#pragma unroll
            for (int i = 0; i < 2; i++) {
                uint4 v;
                v.x = pack_h2(brege[i].x, brego[i].x);
                v.y = pack_h2(brege[i].y, brego[i].y);
                v.z = pack_h2(brege[i].z, brego[i].z);
                v.w = pack_h2(brege[i].w, brego[i].w);
                *(uint4*)&B32[(b_kp + i * 8) * SBU + b_px] = v;
            }
        } else {
            // interleave halves: out u32 j = (even.half[j], odd.half[j])
            uint4 v0, v1;
            v0.x = __byte_perm(hbe.x, hbo.x, 0x5410);
            v0.y = __byte_perm(hbe.x, hbo.x, 0x7632);
            v0.z = __byte_perm(hbe.y, hbo.y, 0x5410);
            v0.w = __byte_perm(hbe.y, hbo.y, 0x7632);
            v1.x = __byte_perm(hbe.z, hbo.z, 0x5410);
            v1.y = __byte_perm(hbe.z, hbo.z, 0x7632);
            v1.z = __byte_perm(hbe.w, hbo.w, 0x5410);
            v1.w = __byte_perm(hbe.w, hbo.w, 0x7632);
            *(uint4*)&B32[h_rp * SBU + h_px]     = v0;
            *(uint4*)&B32[h_rp * SBU + h_px + 4] = v1;
        }
    };

#pragma unroll 1
    for (int mt = 0; mt < NMT; mt++) {
        if (MODE == 0) {
            Ag = win + (size_t)(mt * BM) * CIN;
            Cg = g_qkv + ((size_t)b * C3 + mt * BM) * HW;
        } else {
            Ag = g_M + (size_t)b * CIN * CIN;
            Cg = outp + (size_t)b * CIN * HW;
        }

        float c[3][8][4];
#pragma unroll
        for (int i = 0; i < 3; i++)
#pragma unroll
            for (int j = 0; j < 8; j++)
#pragma unroll
                for (int q = 0; q < 4; q++) c[i][j][q] = 0.0f;

        loadA(0); loadB(0);
        storeA(0); storeB(0);
        __syncthreads();

#pragma unroll 1
        for (int t = 0; t < 6; t++) {
            if (t < 5) { loadA(t + 1); loadB(t + 1); }
            const int s = t & 1;
            const uint32_t* A32 = smem32 + s * STAGE_U32;
            const uint32_t* B32 = smem32 + s * STAGE_U32 + AS_U32;
#pragma unroll
            for (int ks = 0; ks < 2; ks++) {
                const int abase = ks * 8;
                uint32_t af[3][4], bf[8][2];
#pragma unroll
                for (int ms = 0; ms < 3; ms++) {
                    const int mrow = m0w + ms * 16 + g;
                    af[ms][0] = A32[(mrow)     * SA_U32 + abase + cq];
                    af[ms][1] = A32[(mrow + 8) * SA_U32 + abase + cq];
                    af[ms][2] = A32[(mrow)     * SA_U32 + abase + 4 + cq];
                    af[ms][3] = A32[(mrow + 8) * SA_U32 + abase + 4 + cq];
                }
#pragma unroll
                for (int ns = 0; ns < 8; ns++) {
                    const int ncol = n0w + ns * 8 + g;
                    bf[ns][0] = B32[(ks * 8 + cq)     * SBU + ncol];
                    bf[ns][1] = B32[(ks * 8 + cq + 4) * SBU + ncol];
                }
#pragma unroll
                for (int ms = 0; ms < 3; ms++)
#pragma unroll
                    for (int ns = 0; ns < 8; ns++)
                        mma_f16_16x8x16(c[ms][ns][0], c[ms][ns][1], c[ms][ns][2], c[ms][ns][3],
                                        af[ms][0], af[ms][1], af[ms][2], af[ms][3],
                                        bf[ns][0], bf[ns][1]);
            }
            if (t < 5) {
                storeA((t + 1) & 1); storeB((t + 1) & 1);
                __syncthreads();
            }
        }

#pragma unroll
        for (int ms = 0; ms < 3; ms++) {
            const int m = m0w + ms * 16 + g;
#pragma unroll
            for (int ns = 0; ns < 8; ns++) {
                const int n = pix0 + n0w + ns * 8 + cq * 2;
                *(float2*)&Cg[(size_t)m * HW + n]       = make_float2(c[ms][ns][0], c[ms][ns][1]);
                *(float2*)&Cg[(size_t)(m + 8) * HW + n] = make_float2(c[ms][ns][2], c[ms][ns][3]);
            }
        }
        if (mt + 1 < NMT) __syncthreads();
    }
}

// ---------------- depthwise 3x3 + fused sumsq; fp32 in, fp16 out ----------------
__global__ void __launch_bounds__(256) dwconv3x3_kernel(const float* __restrict__ w)
{
    const int bc = blockIdx.x;
    const int ch = bc % C3;
    const int b  = bc / C3;
    const float* ip = g_qkv  + (size_t)bc * HW;
    __half*      op = g_qkvh + (size_t)bc * HW;

    __shared__ float s[34][258];
    const int tid = threadIdx.x;
    const int y0  = blockIdx.y * 32;

    for (int i = tid; i < 34 * 256; i += 256) {
        const int r = i >> 8, xc = i & 255;
        const int y = y0 + r - 1;
        s[r][xc + 1] = (y >= 0 && y < HEI) ? ip[y * WID + xc] : 0.0f;
    }
    if (tid < 34) { s[tid][0] = 0.0f; s[tid][257] = 0.0f; }

    float wr[9];
#pragma unroll
    for (int i = 0; i < 9; i++) wr[i] = w[ch * 9 + i];
    __syncthreads();

    float ssq = 0.0f;
#pragma unroll 4
    for (int r = 0; r < 32; r++) {
        float acc = 0.0f;
#pragma unroll
        for (int dy = 0; dy < 3; dy++)
#pragma unroll
            for (int dx = 0; dx < 3; dx++)
                acc = fmaf(s[r + dy][tid + dx], wr[dy * 3 + dx], acc);
        op[(y0 + r) * WID + tid] = __float2half_rn(acc);
        ssq = fmaf(acc, acc, ssq);   // sumsq on fp32 pre-rounded values
    }

    if (ch < 2 * CIN) {
        __shared__ float red[8];
        const int lane = tid & 31, wp = tid >> 5;
#pragma unroll
        for (int o = 16; o; o >>= 1) ssq += __shfl_down_sync(0xffffffffu, ssq, o);
        if (lane == 0) red[wp] = ssq;
        __syncthreads();
        if (tid == 0) {
            float t = 0.0f;
#pragma unroll
            for (int i = 0; i < 8; i++) t += red[i];
            atomicAdd(&g_sums[b * 2 * CIN + ch], t);
        }
    }
}

// ---------------- fp16 tensor-core gram, cp.async double-buffered ----------------
// G[b,h,:,:] (24x24) += q[24, px] @ k[24, px]^T, fp16 inputs, fp32 accum.
#define GP      32            // pixel chunks per (b,h)
#define GPX     (HW / GP)     // 2048 pixels per block
#define GSUB    256           // pixels per SMEM subtile
#define GNIT    (GPX / GSUB)  // 8
#define GSTR    132           // u32 per row (128 data + 4 pad); 132%32==4
#define GQ_U32  (32 * GSTR)   // q rows 0..31 (24..31 zero)
#define GK_U32  (HDIM * GSTR)
#define GSTAGE  (GQ_U32 + GK_U32)     // 7392 u32
#define GRED    (8 * HDIM * HDIM)
#define GRAM_SMEM_BYTES ((2 * GSTAGE + GRED) * 4)   // 77568

__global__ void __launch_bounds__(256) gram_tc_kernel()
{
    extern __shared__ uint32_t gsm[];
    float* red = (float*)(gsm + 2 * GSTAGE);

    const int bh = blockIdx.y;
    const int b = bh >> 3, h = bh & 7;
    const int px_base = blockIdx.x * GPX;
    const __half* qg = g_qkvh + ((size_t)b * C3 + h * HDIM) * HW;
    const __half* kg = qg + (size_t)CIN * HW;

    const int tid  = threadIdx.x;
    const int warp = tid >> 5;
    const int lane = tid & 31;
    const int g    = lane >> 2;
    const int cq   = lane & 3;

    const uint32_t smb = smem_u32(gsm);

    // zero q pad rows 24..31 in both stages
    for (int i = tid; i < 8 * GSTR; i += 256) {
        gsm[24 * GSTR + i] = 0u;
        gsm[GSTAGE + 24 * GSTR + i] = 0u;
    }

    // 1536 x 16B chunks per stage (48 rows x 32 chunks), 6 per thread
    auto issue_stage = [&](int it, int s) {
        const int px0 = px_base + it * GSUB;
        const uint32_t sb = smb + (uint32_t)(s * GSTAGE) * 4u;
#pragma unroll
        for (int j = 0; j < 6; j++) {
            const int idx = tid + j * 256;
            const int row48 = idx >> 5;
            const int c8    = idx & 31;        // 8-half chunk within row
            const int r     = (row48 < HDIM) ? row48 : row48 - HDIM;
            const __half* src = ((row48 < HDIM) ? qg : kg) + (size_t)r * HW + px0 + c8 * 8;
            const uint32_t dst = sb + (uint32_t)(((row48 < HDIM) ? r * GSTR
                                     : GQ_U32 + r * GSTR) + c8 * 4) * 4u;
            cp_async16(dst, src);
        }
    };

    float c[2][3][4];
#pragma unroll
    for (int mt = 0; mt < 2; mt++)
#pragma unroll
        for (int nt = 0; nt < 3; nt++)
#pragma unroll
            for (int q = 0; q < 4; q++) c[mt][nt][q] = 0.0f;

    issue_stage(0, 0);
    CP_COMMIT();

#pragma unroll 1
    for (int it = 0; it < GNIT; it++) {
        if (it + 1 < GNIT) {
            issue_stage(it + 1, (it + 1) & 1);
            CP_COMMIT();
            CP_WAIT1();
        } else {
            CP_WAIT0();
        }
        __syncthreads();

        const uint32_t* qs = gsm + (it & 1) * GSTAGE;
        const uint32_t* ks = qs + GQ_U32;

        // warp covers pixels [warp*32, warp*32+32): 2 k16 steps
#pragma unroll
        for (int s16 = 0; s16 < 2; s16++) {
            const int kbu = warp * 16 + s16 * 8;     // u32 offset of k16 window
            uint32_t af[2][4], bf[3][2];
#pragma unroll
            for (int mt = 0; mt < 2; mt++) {
                const int r0 = mt * 16 + g;
                af[mt][0] = qs[(r0)     * GSTR + kbu + cq];
                af[mt][1] = qs[(r0 + 8) * GSTR + kbu + cq];
                af[mt][2] = qs[(r0)     * GSTR + kbu + cq + 4];
                af[mt][3] = qs[(r0 + 8) * GSTR + kbu + cq + 4];
            }
#pragma unroll
            for (int nt = 0; nt < 3; nt++) {
                const int er = nt * 8 + g;
                bf[nt][0] = ks[er * GSTR + kbu + cq];
                bf[nt][1] = ks[er * GSTR + kbu + cq + 4];
            }
#pragma unroll
            for (int mt = 0; mt < 2; mt++)
#pragma unroll
                for (int nt = 0; nt < 3; nt++)
                    mma_f16_16x8x16(c[mt][nt][0], c[mt][nt][1], c[mt][nt][2], c[mt][nt][3],
                                    af[mt][0], af[mt][1], af[mt][2], af[mt][3],
                                    bf[nt][0], bf[nt][1]);
        }
        __syncthreads();
    }

    float* rw = red + warp * (HDIM * HDIM);
#pragma unroll
    for (int mt = 0; mt < 2; mt++) {
        const int d = mt * 16 + g;
#pragma unroll
        for (int nt = 0; nt < 3; nt++) {
            const int e = nt * 8 + cq * 2;
            rw[d * HDIM + e]     = c[mt][nt][0];
            rw[d * HDIM + e + 1] = c[mt][nt][1];
            if (d + 8 < HDIM) {
                rw[(d + 8) * HDIM + e]     = c[mt][nt][2];
                rw[(d + 8) * HDIM + e + 1] = c[mt][nt][3];
            }
        }
    }
    __syncthreads();
    for (int i = tid; i < HDIM * HDIM; i += 256) {
        float s = 0.0f;
#pragma unroll
        for (int w2 = 0; w2 < 8; w2++) s += red[w2 * (HDIM * HDIM) + i];
        atomicAdd(&g_gram[bh * HDIM * HDIM + i], s);
    }
}

// ---------------- softmax + fold projection: M = proj * blockdiag(attn) ----------------
__global__ void __launch_bounds__(256) attn_proj_kernel(
    const float* __restrict__ temp, const float* __restrict__ projw)
{
    const int h = blockIdx.x, b = blockIdx.y;
    __shared__ float attn[HDIM][HDIM];
    __shared__ float nq[HDIM], nk[HDIM];
    const int tid = threadIdx.x;

    if (tid < HDIM) {
        nq[tid] = fmaxf(sqrtf(g_sums[b * 2 * CIN + h * HDIM + tid]), 1e-12f);
        nk[tid] = fmaxf(sqrtf(g_sums[b * 2 * CIN + CIN + h * HDIM + tid]), 1e-12f);
    }
    __syncthreads();

    if (tid < HDIM) {
        const float t = temp[h];
        const float* gg = g_gram + ((b * NHEADS + h) * HDIM + tid) * HDIM;
        float row[HDIM];
        float mx = -1e30f;
        const float inq = 1.0f / nq[tid];
#pragma unroll
        for (int e = 0; e < HDIM; e++) {
            row[e] = gg[e] * t * inq / nk[e];
            mx = fmaxf(mx, row[e]);
        }
        float ssum = 0.0f;
#pragma unroll
        for (int e = 0; e < HDIM; e++) { row[e] = expf(row[e] - mx); ssum += row[e]; }
        const float inv = 1.0f / ssum;
#pragma unroll
        for (int e = 0; e < HDIM; e++) attn[tid][e] = row[e] * inv;
    }
    __syncthreads();

    for (int idx = tid; idx < CIN * HDIM; idx += 256) {
        const int o = idx / HDIM, e = idx % HDIM;
        float ssum = 0.0f;
#pragma unroll
        for (int d = 0; d < HDIM; d++)
            ssum = fmaf(projw[o * CIN + h * HDIM + d], attn[d][e], ssum);
        g_M[(size_t)b * CIN * CIN + o * CIN + h * HDIM + e] = ssum;
    }
}

// ---------------- launch ----------------
extern "C" void kernel_launch(void* const* d_in, const int* in_sizes, int n_in,
                              void* d_out, int out_size)
{
    const float *x = nullptr, *qkvw = nullptr, *dww = nullptr, *projw = nullptr, *temp = nullptr;
    for (int i = 0; i < n_in; i++) {
        switch (in_sizes[i]) {
            case NB * CIN * HW:   x     = (const float*)d_in[i]; break;
            case C3 * CIN:        qkvw  = (const float*)d_in[i]; break;
            case C3 * 9:          dww   = (const float*)d_in[i]; break;
            case CIN * CIN:       projw = (const float*)d_in[i]; break;
            case NHEADS:          temp  = (const float*)d_in[i]; break;
        }
    }
    float* out = (float*)d_out;

    static int configured = 0;
    if (!configured) {
        cudaFuncSetAttribute(gemm_mma_kernel<0>, cudaFuncAttributeMaxDynamicSharedMemorySize, GEMM_SMEM_BYTES);
        cudaFuncSetAttribute(gemm_mma_kernel<1>, cudaFuncAttributeMaxDynamicSharedMemorySize, GEMM_SMEM_BYTES);
        cudaFuncSetAttribute(gram_tc_kernel, cudaFuncAttributeMaxDynamicSharedMemorySize, GRAM_SMEM_BYTES);
        configured = 1;
    }

    zero_small_kernel<<<72, 256>>>();

    // qkv 1x1 conv (fp16 mma, 3 channel tiles per block)
    gemm_mma_kernel<0><<<dim3(HW / BN, 1, NB), 256, GEMM_SMEM_BYTES>>>(x, qkvw, nullptr);

    // depthwise 3x3, fp32 -> fp16 out (+ fused q/k sum-of-squares)
    dwconv3x3_kernel<<<dim3(NB * C3, HEI / 32), 256>>>(dww);

    // fp16 tensor-core gram (cp.async pipelined)
    gram_tc_kernel<<<dim3(GP, NB * NHEADS), 256, GRAM_SMEM_BYTES>>>();

    // softmax + fold projection into per-batch M
    attn_proj_kernel<<<dim3(NHEADS, NB), 256>>>(temp, projw);

    // final: out = M @ v (fp16 mma, fp16 B loads)
    gemm_mma_kernel<1><<<dim3(HW / BN, 1, NB), 256, GEMM_SMEM_BYTES>>>(nullptr, nullptr, out);
}